// round 5
// baseline (speedup 1.0000x reference)
#include <cuda_runtime.h>
#include <cuda_bf16.h>
#include <math.h>
#include <stdint.h>

// ---------------------------------------------------------------------------
// Problem constants
// ---------------------------------------------------------------------------
#define BATCH 2
#define SEQ 2048
#define HIDDEN 1024
#define NHEAD 16
#define HDIM 64
#define M_TOK (BATCH * SEQ)          // 4096
#define QKV_N (3 * HIDDEN)           // 3072
#define LD32 (QKV_N / 2)             // 1536 u32 per token row (qkv planes)

// Scratch (__device__ globals per allocation rules)
__device__ uint32_t g_qh[(size_t)M_TOK * LD32];      // qkv hi plane
__device__ uint32_t g_ql[(size_t)M_TOK * LD32];      // qkv lo plane
__device__ uint32_t g_hh[(size_t)M_TOK * 512];       // hidden split hi
__device__ uint32_t g_hl[(size_t)M_TOK * 512];       // hidden split lo
__device__ uint32_t g_wh[(size_t)QKV_N * 512];       // w_attn^T hi  [n][kp]
__device__ uint32_t g_wl[(size_t)QKV_N * 512];       // w_attn^T lo
__device__ uint32_t g_ph[(size_t)HIDDEN * 512];      // w_proj^T hi
__device__ uint32_t g_pl[(size_t)HIDDEN * 512];      // w_proj^T lo
__device__ uint32_t g_ah[(size_t)M_TOK * 512];       // attn out hi
__device__ uint32_t g_al[(size_t)M_TOK * 512];       // attn out lo

// ---------------------------------------------------------------------------
// Helpers
// ---------------------------------------------------------------------------
__device__ __forceinline__ void split2(float x, float y,
                                       uint32_t& hi, uint32_t& lo) {
    __nv_bfloat162 h = __floats2bfloat162_rn(x, y);
    float2 hf = __bfloat1622float2(h);
    __nv_bfloat162 l = __floats2bfloat162_rn(x - hf.x, y - hf.y);
    hi = *reinterpret_cast<uint32_t*>(&h);
    lo = *reinterpret_cast<uint32_t*>(&l);
}

__device__ __forceinline__ void mma_bf16(float* c, uint32_t a0, uint32_t a1,
                                         uint32_t a2, uint32_t a3,
                                         uint32_t b0, uint32_t b1) {
    asm volatile(
        "mma.sync.aligned.m16n8k16.row.col.f32.bf16.bf16.f32 "
        "{%0,%1,%2,%3}, {%4,%5,%6,%7}, {%8,%9}, {%0,%1,%2,%3};"
        : "+f"(c[0]), "+f"(c[1]), "+f"(c[2]), "+f"(c[3])
        : "r"(a0), "r"(a1), "r"(a2), "r"(a3), "r"(b0), "r"(b1));
}

// ---------------------------------------------------------------------------
// Prep kernel 1: elementwise split fp32 -> bf16 hi/lo planes (pairs)
// ---------------------------------------------------------------------------
__global__ __launch_bounds__(256)
void split_pairs(const float2* __restrict__ src,
                 uint32_t* __restrict__ dh, uint32_t* __restrict__ dl, int n)
{
    int i = blockIdx.x * 256 + threadIdx.x;
    if (i < n) {
        float2 v = src[i];
        uint32_t h, l;
        split2(v.x, v.y, h, l);
        dh[i] = h;
        dl[i] = l;
    }
}

// ---------------------------------------------------------------------------
// Prep kernel 2: transpose + split  W[K][N] -> Wt hi/lo [N][K/2] (u32 pairs)
// Tile: 64 k x 32 n, 256 threads.
// ---------------------------------------------------------------------------
__global__ __launch_bounds__(256)
void transpose_split(const float* __restrict__ W,
                     uint32_t* __restrict__ th, uint32_t* __restrict__ tl,
                     int K, int N)
{
    __shared__ float s[64][33];
    const int tid = threadIdx.x;
    const int k0 = blockIdx.y * 64;
    const int n0 = blockIdx.x * 32;

#pragma unroll
    for (int i = 0; i < 8; i++) {
        int idx = tid + i * 256;         // 0..2047
        int nl = idx & 31;
        int kl = idx >> 5;               // 0..63
        s[kl][nl] = W[(size_t)(k0 + kl) * N + n0 + nl];
    }
    __syncthreads();

    const int K2 = K >> 1;
#pragma unroll
    for (int i = 0; i < 4; i++) {
        int idx = tid + i * 256;         // 0..1023
        int kp = idx & 31;               // 0..31
        int nl = idx >> 5;               // 0..31
        uint32_t h, l;
        split2(s[2 * kp][nl], s[2 * kp + 1][nl], h, l);
        size_t o = (size_t)(n0 + nl) * K2 + (k0 >> 1) + kp;
        th[o] = h;
        tl[o] = l;
    }
}

// ---------------------------------------------------------------------------
// bf16x3 GEMM on pre-split planes:
//   C[M,N] = A[M,K] @ B[K,N] + bias,  A as Ah/Al [M][K/2], B as Bh/Bl [N][K/2]
// BM=BN=128, BK=16 (8 u32), 256 thr = 8 warps (2m x 4n), warp 64x32.
// Smem: 4 planes [128 rows][stride 12 u32] per buffer, double buffered = 48KB.
// Bank check (frag LDS): addr = row*12 + t, rows g: 12g mod 32 covers all banks.
// mode 0: fp32 C + bias. mode 1: split planes Chi/Clo + bias.
// ---------------------------------------------------------------------------
#define PSTR 12
#define PLANE (128 * PSTR)

__global__ __launch_bounds__(256, 2)
void gemm_planes(const uint32_t* __restrict__ Ah, const uint32_t* __restrict__ Al,
                 const uint32_t* __restrict__ Bh, const uint32_t* __restrict__ Bl,
                 const float* __restrict__ bias,
                 float* __restrict__ Cf,
                 uint32_t* __restrict__ Chi, uint32_t* __restrict__ Clo,
                 int M, int N, int K2, int mode)
{
    __shared__ uint32_t sm4[2][4][PLANE];   // [buf][plane][...]  48KB

    const int tid  = threadIdx.x;
    const int warp = tid >> 5;
    const int lane = tid & 31;
    const int g = lane >> 2;
    const int t = lane & 3;
    const int wm = (warp >> 2) * 64;
    const int wn = (warp & 3) * 32;
    const int brow = blockIdx.y * 128;
    const int bcol = blockIdx.x * 128;

    const int srow  = tid >> 1;       // 0..127
    const int shalf = (tid & 1) * 4;  // 0 or 4 (u32)

    float acc[4][4][4];
#pragma unroll
    for (int mt = 0; mt < 4; mt++)
#pragma unroll
        for (int nt = 0; nt < 4; nt++)
#pragma unroll
            for (int r = 0; r < 4; r++) acc[mt][nt][r] = 0.0f;

    uint4 pf[4];
    auto prefetch = [&](int kp0) {
        pf[0] = *(const uint4*)&Ah[(size_t)(brow + srow) * K2 + kp0 + shalf];
        pf[1] = *(const uint4*)&Al[(size_t)(brow + srow) * K2 + kp0 + shalf];
        pf[2] = *(const uint4*)&Bh[(size_t)(bcol + srow) * K2 + kp0 + shalf];
        pf[3] = *(const uint4*)&Bl[(size_t)(bcol + srow) * K2 + kp0 + shalf];
    };
    auto stage = [&](int buf) {
        const int o = srow * PSTR + shalf;
#pragma unroll
        for (int p = 0; p < 4; p++)
            *(uint4*)&sm4[buf][p][o] = pf[p];
    };

    prefetch(0);
    stage(0);
    __syncthreads();

    const int NCH = K2 >> 3;   // chunks of 8 u32 (k16)
    int buf = 0;
    for (int c = 0; c < NCH; c++) {
        const bool has_next = (c + 1) < NCH;
        if (has_next) prefetch((c + 1) * 8);

        const uint32_t* sAh = sm4[buf][0];
        const uint32_t* sAl = sm4[buf][1];
        const uint32_t* sBh = sm4[buf][2];
        const uint32_t* sBl = sm4[buf][3];

        uint32_t bh[4][2], bl[4][2];
#pragma unroll
        for (int nt = 0; nt < 4; nt++) {
            const int col = wn + nt * 8 + g;
            bh[nt][0] = sBh[col * PSTR + t];
            bh[nt][1] = sBh[col * PSTR + t + 4];
            bl[nt][0] = sBl[col * PSTR + t];
            bl[nt][1] = sBl[col * PSTR + t + 4];
        }
#pragma unroll
        for (int mt = 0; mt < 4; mt++) {
            const int r = wm + mt * 16 + g;
            uint32_t ah0 = sAh[r * PSTR + t];
            uint32_t ah1 = sAh[(r + 8) * PSTR + t];
            uint32_t ah2 = sAh[r * PSTR + t + 4];
            uint32_t ah3 = sAh[(r + 8) * PSTR + t + 4];
            uint32_t al0 = sAl[r * PSTR + t];
            uint32_t al1 = sAl[(r + 8) * PSTR + t];
            uint32_t al2 = sAl[r * PSTR + t + 4];
            uint32_t al3 = sAl[(r + 8) * PSTR + t + 4];
#pragma unroll
            for (int nt = 0; nt < 4; nt++) {
                mma_bf16(acc[mt][nt], ah0, ah1, ah2, ah3, bh[nt][0], bh[nt][1]);
                mma_bf16(acc[mt][nt], ah0, ah1, ah2, ah3, bl[nt][0], bl[nt][1]);
                mma_bf16(acc[mt][nt], al0, al1, al2, al3, bh[nt][0], bh[nt][1]);
            }
        }

        if (has_next) {
            stage(buf ^ 1);
            __syncthreads();
            buf ^= 1;
        }
    }

    // epilogue: c-frag rows g,g+8; cols 2t,2t+1
#pragma unroll
    for (int nt = 0; nt < 4; nt++) {
        const int col = bcol + wn + nt * 8 + 2 * t;
        const float2 bv = *(const float2*)(bias + col);
#pragma unroll
        for (int mt = 0; mt < 4; mt++) {
            const int row0 = brow + wm + mt * 16 + g;
            float v00 = acc[mt][nt][0] + bv.x, v01 = acc[mt][nt][1] + bv.y;
            float v10 = acc[mt][nt][2] + bv.x, v11 = acc[mt][nt][3] + bv.y;
            if (mode == 0) {
                *(float2*)(Cf + (size_t)row0 * N + col)       = make_float2(v00, v01);
                *(float2*)(Cf + (size_t)(row0 + 8) * N + col) = make_float2(v10, v11);
            } else {
                uint32_t h, l;
                size_t i0 = ((size_t)row0 * N + col) >> 1;
                split2(v00, v01, h, l);  Chi[i0] = h;  Clo[i0] = l;
                size_t i1 = ((size_t)(row0 + 8) * N + col) >> 1;
                split2(v10, v11, h, l);  Chi[i1] = h;  Clo[i1] = l;
            }
        }
    }
}

// ---------------------------------------------------------------------------
// Tensor-core flash attention, bf16x3, causal, NO 1/sqrt(d) scaling.
// Same core as R3; epilogue now writes split bf16 planes for the proj GEMM.
// ---------------------------------------------------------------------------
#define KSTR 36
#define VSTR 72

__global__ __launch_bounds__(256)
void flash_bf16x3(const uint32_t* __restrict__ qh,
                  const uint32_t* __restrict__ ql,
                  uint32_t* __restrict__ aH, uint32_t* __restrict__ aL)
{
    __shared__ uint32_t Ksh[64 * KSTR], Ksl[64 * KSTR];
    __shared__ uint32_t Vsh[32 * VSTR], Vsl[32 * VSTR];

    const int qbx = blockIdx.x;
    const int h   = blockIdx.y;
    const int b   = blockIdx.z;

    const int tid  = threadIdx.x;
    const int wid  = tid >> 5;
    const int lane = tid & 31;
    const int g = lane >> 2;
    const int t = lane & 3;

    const int qoff = h * 32;
    const int koff = 512 + h * 32;
    const int voff = 1024 + h * 32;

    const int wq = qbx * 128 + wid * 16;
    const size_t rowA = (size_t)(b * SEQ + wq + g) * LD32;
    const size_t rowB = rowA + 8 * LD32;

    uint32_t qfh[4][4], qfl[4][4];
#pragma unroll
    for (int s = 0; s < 4; s++) {
        qfh[s][0] = qh[rowA + qoff + s * 8 + t];
        qfh[s][1] = qh[rowB + qoff + s * 8 + t];
        qfh[s][2] = qh[rowA + qoff + s * 8 + t + 4];
        qfh[s][3] = qh[rowB + qoff + s * 8 + t + 4];
        qfl[s][0] = ql[rowA + qoff + s * 8 + t];
        qfl[s][1] = ql[rowB + qoff + s * 8 + t];
        qfl[s][2] = ql[rowA + qoff + s * 8 + t + 4];
        qfl[s][3] = ql[rowB + qoff + s * 8 + t + 4];
    }

    float oa[8][4];
#pragma unroll
    for (int nt = 0; nt < 8; nt++)
#pragma unroll
        for (int r = 0; r < 4; r++) oa[nt][r] = 0.0f;
    float m0 = -1e30f, m1 = -1e30f, l0 = 0.0f, l1 = 0.0f;

    const int r0g = wq + g;
    const int r1g = wq + g + 8;
    const int nblocks = 2 * qbx + 2;

    for (int jb = 0; jb < nblocks; jb++) {
        __syncthreads();
#pragma unroll
        for (int i = 0; i < 8; i++) {
            int idx = tid + i * 256;
            int tok = idx >> 5, dp = idx & 31;
            size_t gi = (size_t)(b * SEQ + jb * 64 + tok) * LD32 + koff + dp;
            Ksh[tok * KSTR + dp] = qh[gi];
            Ksl[tok * KSTR + dp] = ql[gi];
        }
#pragma unroll
        for (int i = 0; i < 4; i++) {
            int idx = tid + i * 256;
            int r = idx >> 5, j = idx & 31;
            size_t g0 = (size_t)(b * SEQ + jb * 64 + 2 * r) * LD32 + voff + j;
            uint32_t a0 = qh[g0], b0 = qh[g0 + LD32];
            Vsh[r * VSTR + 2 * j]     = __byte_perm(a0, b0, 0x5410);
            Vsh[r * VSTR + 2 * j + 1] = __byte_perm(a0, b0, 0x7632);
            uint32_t a1 = ql[g0], b1 = ql[g0 + LD32];
            Vsl[r * VSTR + 2 * j]     = __byte_perm(a1, b1, 0x5410);
            Vsl[r * VSTR + 2 * j + 1] = __byte_perm(a1, b1, 0x7632);
        }
        __syncthreads();

        if (jb * 64 > wq + 15) continue;

        float sc[8][4];
#pragma unroll
        for (int nt = 0; nt < 8; nt++)
#pragma unroll
            for (int r = 0; r < 4; r++) sc[nt][r] = 0.0f;

#pragma unroll
        for (int s = 0; s < 4; s++) {
#pragma unroll
            for (int nt = 0; nt < 8; nt++) {
                const int tok = nt * 8 + g;
                uint32_t kh0 = Ksh[tok * KSTR + s * 8 + t];
                uint32_t kh1 = Ksh[tok * KSTR + s * 8 + t + 4];
                uint32_t kl0 = Ksl[tok * KSTR + s * 8 + t];
                uint32_t kl1 = Ksl[tok * KSTR + s * 8 + t + 4];
                mma_bf16(sc[nt], qfh[s][0], qfh[s][1], qfh[s][2], qfh[s][3], kh0, kh1);
                mma_bf16(sc[nt], qfh[s][0], qfh[s][1], qfh[s][2], qfh[s][3], kl0, kl1);
                mma_bf16(sc[nt], qfl[s][0], qfl[s][1], qfl[s][2], qfl[s][3], kh0, kh1);
            }
        }

        if (jb * 64 + 63 > wq) {
#pragma unroll
            for (int nt = 0; nt < 8; nt++) {
                int c = jb * 64 + nt * 8 + 2 * t;
                if (c > r0g)     sc[nt][0] = -1e30f;
                if (c + 1 > r0g) sc[nt][1] = -1e30f;
                if (c > r1g)     sc[nt][2] = -1e30f;
                if (c + 1 > r1g) sc[nt][3] = -1e30f;
            }
        }

        float mx0 = -1e30f, mx1 = -1e30f;
#pragma unroll
        for (int nt = 0; nt < 8; nt++) {
            mx0 = fmaxf(mx0, fmaxf(sc[nt][0], sc[nt][1]));
            mx1 = fmaxf(mx1, fmaxf(sc[nt][2], sc[nt][3]));
        }
#pragma unroll
        for (int off = 1; off <= 2; off <<= 1) {
            mx0 = fmaxf(mx0, __shfl_xor_sync(0xffffffffu, mx0, off));
            mx1 = fmaxf(mx1, __shfl_xor_sync(0xffffffffu, mx1, off));
        }
        float mn0 = fmaxf(m0, mx0), mn1 = fmaxf(m1, mx1);
        float corr0 = __expf(m0 - mn0), corr1 = __expf(m1 - mn1);
        float s0 = 0.0f, s1 = 0.0f;
#pragma unroll
        for (int nt = 0; nt < 8; nt++) {
            sc[nt][0] = __expf(sc[nt][0] - mn0);
            sc[nt][1] = __expf(sc[nt][1] - mn0);
            sc[nt][2] = __expf(sc[nt][2] - mn1);
            sc[nt][3] = __expf(sc[nt][3] - mn1);
            s0 += sc[nt][0] + sc[nt][1];
            s1 += sc[nt][2] + sc[nt][3];
        }
#pragma unroll
        for (int off = 1; off <= 2; off <<= 1) {
            s0 += __shfl_xor_sync(0xffffffffu, s0, off);
            s1 += __shfl_xor_sync(0xffffffffu, s1, off);
        }
        l0 = l0 * corr0 + s0;  m0 = mn0;
        l1 = l1 * corr1 + s1;  m1 = mn1;
#pragma unroll
        for (int nt = 0; nt < 8; nt++) {
            oa[nt][0] *= corr0;  oa[nt][1] *= corr0;
            oa[nt][2] *= corr1;  oa[nt][3] *= corr1;
        }

#pragma unroll
        for (int s = 0; s < 4; s++) {
            uint32_t ph[4], pl[4];
            split2(sc[2 * s][0],     sc[2 * s][1],     ph[0], pl[0]);
            split2(sc[2 * s][2],     sc[2 * s][3],     ph[1], pl[1]);
            split2(sc[2 * s + 1][0], sc[2 * s + 1][1], ph[2], pl[2]);
            split2(sc[2 * s + 1][2], sc[2 * s + 1][3], ph[3], pl[3]);
#pragma unroll
            for (int nt = 0; nt < 8; nt++) {
                const int d = nt * 8 + g;
                uint32_t vh0 = Vsh[(s * 8 + t) * VSTR + d];
                uint32_t vh1 = Vsh[(s * 8 + t + 4) * VSTR + d];
                uint32_t vl0 = Vsl[(s * 8 + t) * VSTR + d];
                uint32_t vl1 = Vsl[(s * 8 + t + 4) * VSTR + d];
                mma_bf16(oa[nt], ph[0], ph[1], ph[2], ph[3], vh0, vh1);
                mma_bf16(oa[nt], ph[0], ph[1], ph[2], ph[3], vl0, vl1);
                mma_bf16(oa[nt], pl[0], pl[1], pl[2], pl[3], vh0, vh1);
            }
        }
    }

    // epilogue: write split bf16 planes [tok][512 u32]
    const float inv0 = 1.0f / l0, inv1 = 1.0f / l1;
    const size_t o0 = (size_t)(b * SEQ + r0g) * 512 + h * 32;
    const size_t o1 = (size_t)(b * SEQ + r1g) * 512 + h * 32;
#pragma unroll
    for (int nt = 0; nt < 8; nt++) {
        const int dp = nt * 4 + t;
        uint32_t h0, l0u, h1, l1u;
        split2(oa[nt][0] * inv0, oa[nt][1] * inv0, h0, l0u);
        split2(oa[nt][2] * inv1, oa[nt][3] * inv1, h1, l1u);
        aH[o0 + dp] = h0;  aL[o0 + dp] = l0u;
        aH[o1 + dp] = h1;  aL[o1 + dp] = l1u;
    }
}

// ---------------------------------------------------------------------------
// Launch
// ---------------------------------------------------------------------------
extern "C" void kernel_launch(void* const* d_in, const int* in_sizes, int n_in,
                              void* d_out, int out_size)
{
    const float* hidden = (const float*)d_in[0];
    const float* w_attn = (const float*)d_in[1];
    const float* b_attn = (const float*)d_in[2];
    const float* w_proj = (const float*)d_in[3];
    const float* b_proj = (const float*)d_in[4];
    float* out = (float*)d_out;

    uint32_t *qh, *ql, *hh, *hl, *wh, *wl, *ph, *pl, *ah, *al;
    cudaGetSymbolAddress((void**)&qh, g_qh);
    cudaGetSymbolAddress((void**)&ql, g_ql);
    cudaGetSymbolAddress((void**)&hh, g_hh);
    cudaGetSymbolAddress((void**)&hl, g_hl);
    cudaGetSymbolAddress((void**)&wh, g_wh);
    cudaGetSymbolAddress((void**)&wl, g_wl);
    cudaGetSymbolAddress((void**)&ph, g_ph);
    cudaGetSymbolAddress((void**)&pl, g_pl);
    cudaGetSymbolAddress((void**)&ah, g_ah);
    cudaGetSymbolAddress((void**)&al, g_al);

    // 0) prep: split hidden; transpose+split weights
    {
        const int n = M_TOK * 512;   // fp32 pairs in hidden
        split_pairs<<<(n + 255) / 256, 256>>>((const float2*)hidden, hh, hl, n);
        dim3 gw(QKV_N / 32, HIDDEN / 64);
        transpose_split<<<gw, 256>>>(w_attn, wh, wl, HIDDEN, QKV_N);
        dim3 gp(HIDDEN / 32, HIDDEN / 64);
        transpose_split<<<gp, 256>>>(w_proj, ph, pl, HIDDEN, HIDDEN);
    }
    // 1) QKV projection -> split qkv planes
    {
        dim3 grid(QKV_N / 128, M_TOK / 128);
        gemm_planes<<<grid, 256>>>(hh, hl, wh, wl, b_attn,
                                   nullptr, qh, ql,
                                   M_TOK, QKV_N, HIDDEN / 2, 1);
    }
    // 2) flash attention -> split attn planes
    {
        dim3 grid(SEQ / 128, NHEAD, BATCH);
        flash_bf16x3<<<grid, 256>>>(qh, ql, ah, al);
    }
    // 3) output projection -> fp32 out
    {
        dim3 grid(HIDDEN / 128, M_TOK / 128);
        gemm_planes<<<grid, 256>>>(ah, al, ph, pl, b_proj,
                                   out, nullptr, nullptr,
                                   M_TOK, HIDDEN, HIDDEN / 2, 0);
    }
}

// round 6
// speedup vs baseline: 1.0455x; 1.0455x over previous
#include <cuda_runtime.h>
#include <cuda_bf16.h>
#include <math.h>
#include <stdint.h>

// ---------------------------------------------------------------------------
// Problem constants
// ---------------------------------------------------------------------------
#define BATCH 2
#define SEQ 2048
#define HIDDEN 1024
#define NHEAD 16
#define HDIM 64
#define M_TOK (BATCH * SEQ)          // 4096
#define QKV_N (3 * HIDDEN)           // 3072
#define LD32 (QKV_N / 2)             // 1536 u32 per token row (qkv planes)

// Scratch (__device__ globals per allocation rules)
__device__ uint32_t g_qh[(size_t)M_TOK * LD32];      // qkv hi plane
__device__ uint32_t g_ql[(size_t)M_TOK * LD32];      // qkv lo plane
__device__ uint32_t g_hh[(size_t)M_TOK * 512];       // hidden split hi
__device__ uint32_t g_hl[(size_t)M_TOK * 512];       // hidden split lo
__device__ uint32_t g_wh[(size_t)QKV_N * 512];       // w_attn^T hi  [n][kp]
__device__ uint32_t g_wl[(size_t)QKV_N * 512];       // w_attn^T lo
__device__ uint32_t g_ph[(size_t)HIDDEN * 512];      // w_proj^T hi
__device__ uint32_t g_pl[(size_t)HIDDEN * 512];      // w_proj^T lo
__device__ uint32_t g_ah[(size_t)M_TOK * 512];       // attn out hi
__device__ uint32_t g_al[(size_t)M_TOK * 512];       // attn out lo

// ---------------------------------------------------------------------------
// Helpers
// ---------------------------------------------------------------------------
__device__ __forceinline__ void split2(float x, float y,
                                       uint32_t& hi, uint32_t& lo) {
    __nv_bfloat162 h = __floats2bfloat162_rn(x, y);
    float2 hf = __bfloat1622float2(h);
    __nv_bfloat162 l = __floats2bfloat162_rn(x - hf.x, y - hf.y);
    hi = *reinterpret_cast<uint32_t*>(&h);
    lo = *reinterpret_cast<uint32_t*>(&l);
}

__device__ __forceinline__ void mma_bf16(float* c, uint32_t a0, uint32_t a1,
                                         uint32_t a2, uint32_t a3,
                                         uint32_t b0, uint32_t b1) {
    asm volatile(
        "mma.sync.aligned.m16n8k16.row.col.f32.bf16.bf16.f32 "
        "{%0,%1,%2,%3}, {%4,%5,%6,%7}, {%8,%9}, {%0,%1,%2,%3};"
        : "+f"(c[0]), "+f"(c[1]), "+f"(c[2]), "+f"(c[3])
        : "r"(a0), "r"(a1), "r"(a2), "r"(a3), "r"(b0), "r"(b1));
}

__device__ __forceinline__ void ldsm4(uint32_t& r0, uint32_t& r1,
                                      uint32_t& r2, uint32_t& r3, uint32_t a) {
    asm volatile("ldmatrix.sync.aligned.m8n8.x4.shared.b16 {%0,%1,%2,%3}, [%4];"
                 : "=r"(r0), "=r"(r1), "=r"(r2), "=r"(r3) : "r"(a));
}

__device__ __forceinline__ void cp16(uint32_t smem, const void* gmem) {
    asm volatile("cp.async.ca.shared.global [%0], [%1], 16;"
                 :: "r"(smem), "l"(gmem));
}
#define CP_COMMIT() asm volatile("cp.async.commit_group;" ::: "memory")
#define CP_WAIT(n)  asm volatile("cp.async.wait_group %0;" :: "n"(n) : "memory")

// ---------------------------------------------------------------------------
// Prep kernel 1: elementwise split fp32 -> bf16 hi/lo planes (pairs)
// ---------------------------------------------------------------------------
__global__ __launch_bounds__(256)
void split_pairs(const float2* __restrict__ src,
                 uint32_t* __restrict__ dh, uint32_t* __restrict__ dl, int n)
{
    int i = blockIdx.x * 256 + threadIdx.x;
    if (i < n) {
        float2 v = src[i];
        uint32_t h, l;
        split2(v.x, v.y, h, l);
        dh[i] = h;
        dl[i] = l;
    }
}

// ---------------------------------------------------------------------------
// Prep kernel 2: transpose + split  W[K][N] -> Wt hi/lo [N][K/2] (u32 pairs)
// ---------------------------------------------------------------------------
__global__ __launch_bounds__(256)
void transpose_split(const float* __restrict__ W,
                     uint32_t* __restrict__ th, uint32_t* __restrict__ tl,
                     int K, int N)
{
    __shared__ float s[64][33];
    const int tid = threadIdx.x;
    const int k0 = blockIdx.y * 64;
    const int n0 = blockIdx.x * 32;

#pragma unroll
    for (int i = 0; i < 8; i++) {
        int idx = tid + i * 256;
        int nl = idx & 31;
        int kl = idx >> 5;
        s[kl][nl] = W[(size_t)(k0 + kl) * N + n0 + nl];
    }
    __syncthreads();

    const int K2 = K >> 1;
#pragma unroll
    for (int i = 0; i < 4; i++) {
        int idx = tid + i * 256;
        int kp = idx & 31;
        int nl = idx >> 5;
        uint32_t h, l;
        split2(s[2 * kp][nl], s[2 * kp + 1][nl], h, l);
        size_t o = (size_t)(n0 + nl) * K2 + (k0 >> 1) + kp;
        th[o] = h;
        tl[o] = l;
    }
}

// ---------------------------------------------------------------------------
// bf16x3 GEMM on pre-split planes, cp.async 4-stage pipeline + ldmatrix frags.
//   C[M,N] = A[M,K] @ B[K,N] + bias,  A: Ah/Al [M][K2], B: Bh/Bl [N][K2]
// BM=BN=128, chunk = k16 (8 u32). 256 thr = 8 warps (2m x 4n), warp 64x32.
// Smem per stage: 4 planes x [128 rows][stride 12 u32] = 24KB; 4 stages = 96KB.
// Row stride 48B -> ldmatrix 8-row groups hit 8 distinct 16B regions mod 128B.
// ---------------------------------------------------------------------------
#define PSTR 12
#define PLANE_B (128 * PSTR * 4)     // 6144 bytes per plane
#define STAGE_B (4 * PLANE_B)        // 24576 bytes per stage
#define NSTAGE 4
#define GEMM_SMEM (NSTAGE * STAGE_B) // 98304

__global__ __launch_bounds__(256, 2)
void gemm_planes(const uint32_t* __restrict__ Ah, const uint32_t* __restrict__ Al,
                 const uint32_t* __restrict__ Bh, const uint32_t* __restrict__ Bl,
                 const float* __restrict__ bias,
                 float* __restrict__ Cf,
                 uint32_t* __restrict__ Chi, uint32_t* __restrict__ Clo,
                 int M, int N, int K2, int mode)
{
    extern __shared__ uint32_t smem[];
    const uint32_t sb = (uint32_t)__cvta_generic_to_shared(smem);

    const int tid  = threadIdx.x;
    const int warp = tid >> 5;
    const int lane = tid & 31;
    const int g = lane >> 2;
    const int t = lane & 3;
    const int wm = (warp >> 2) * 64;
    const int wn = (warp & 3) * 32;
    const int brow = blockIdx.y * 128;
    const int bcol = blockIdx.x * 128;

    // cp.async mapping: thread -> (row, 16B-half), one per plane
    const int crow  = tid >> 1;
    const int chalf = tid & 1;
    const uint32_t cso = (uint32_t)(crow * 48 + chalf * 16);
    const uint32_t goff = (uint32_t)(chalf * 4);
    const uint32_t* gA[2] = { Ah + (size_t)(brow + crow) * K2 + goff,
                              Al + (size_t)(brow + crow) * K2 + goff };
    const uint32_t* gB[2] = { Bh + (size_t)(bcol + crow) * K2 + goff,
                              Bl + (size_t)(bcol + crow) * K2 + goff };

    auto issue_chunk = [&](int c) {
        const uint32_t base = sb + (uint32_t)((c & (NSTAGE - 1)) * STAGE_B);
        const int kp = c * 8;
        cp16(base + 0 * PLANE_B + cso, gA[0] + kp);
        cp16(base + 1 * PLANE_B + cso, gA[1] + kp);
        cp16(base + 2 * PLANE_B + cso, gB[0] + kp);
        cp16(base + 3 * PLANE_B + cso, gB[1] + kp);
        CP_COMMIT();
    };

    // ldmatrix per-lane address components
    const int laA = (lane & 7) + ((lane >> 3) & 1) * 8;   // row within 16
    const uint32_t kaA = (uint32_t)((lane >> 4) * 16);    // k-byte offset
    const int laB = (lane & 7) + ((lane >> 4) & 1) * 8;
    const uint32_t kaB = (uint32_t)(((lane >> 3) & 1) * 16);

    float acc[4][4][4];
#pragma unroll
    for (int mt = 0; mt < 4; mt++)
#pragma unroll
        for (int nt = 0; nt < 4; nt++)
#pragma unroll
            for (int r = 0; r < 4; r++) acc[mt][nt][r] = 0.0f;

    const int NC = K2 >> 3;

    // prologue: fill stages 0..NSTAGE-2
#pragma unroll
    for (int s = 0; s < NSTAGE - 1; s++) issue_chunk(s);

    for (int c = 0; c < NC; c++) {
        CP_WAIT(NSTAGE - 2);
        __syncthreads();

        if (c + NSTAGE - 1 < NC) issue_chunk(c + NSTAGE - 1);

        const uint32_t base = sb + (uint32_t)((c & (NSTAGE - 1)) * STAGE_B);
        const uint32_t bAh = base;
        const uint32_t bAl = base + PLANE_B;
        const uint32_t bBh = base + 2 * PLANE_B;
        const uint32_t bBl = base + 3 * PLANE_B;

        // B fragments: 2 ldmatrix.x4 per plane (each covers 2 n-tiles)
        uint32_t bh[4][2], bl[4][2];
#pragma unroll
        for (int np = 0; np < 2; np++) {
            const uint32_t ro = (uint32_t)((wn + np * 16 + laB) * 48) + kaB;
            ldsm4(bh[2 * np][0], bh[2 * np][1], bh[2 * np + 1][0], bh[2 * np + 1][1],
                  bBh + ro);
            ldsm4(bl[2 * np][0], bl[2 * np][1], bl[2 * np + 1][0], bl[2 * np + 1][1],
                  bBl + ro);
        }
#pragma unroll
        for (int mt = 0; mt < 4; mt++) {
            const uint32_t ro = (uint32_t)((wm + mt * 16 + laA) * 48) + kaA;
            uint32_t ah0, ah1, ah2, ah3, al0, al1, al2, al3;
            ldsm4(ah0, ah1, ah2, ah3, bAh + ro);
            ldsm4(al0, al1, al2, al3, bAl + ro);
#pragma unroll
            for (int nt = 0; nt < 4; nt++) {
                mma_bf16(acc[mt][nt], ah0, ah1, ah2, ah3, bh[nt][0], bh[nt][1]);
                mma_bf16(acc[mt][nt], ah0, ah1, ah2, ah3, bl[nt][0], bl[nt][1]);
                mma_bf16(acc[mt][nt], al0, al1, al2, al3, bh[nt][0], bh[nt][1]);
            }
        }
    }

    // epilogue: c-frag rows g,g+8; cols 2t,2t+1
#pragma unroll
    for (int nt = 0; nt < 4; nt++) {
        const int col = bcol + wn + nt * 8 + 2 * t;
        const float2 bv = *(const float2*)(bias + col);
#pragma unroll
        for (int mt = 0; mt < 4; mt++) {
            const int row0 = brow + wm + mt * 16 + g;
            float v00 = acc[mt][nt][0] + bv.x, v01 = acc[mt][nt][1] + bv.y;
            float v10 = acc[mt][nt][2] + bv.x, v11 = acc[mt][nt][3] + bv.y;
            if (mode == 0) {
                *(float2*)(Cf + (size_t)row0 * N + col)       = make_float2(v00, v01);
                *(float2*)(Cf + (size_t)(row0 + 8) * N + col) = make_float2(v10, v11);
            } else {
                uint32_t h, l;
                size_t i0 = ((size_t)row0 * N + col) >> 1;
                split2(v00, v01, h, l);  Chi[i0] = h;  Clo[i0] = l;
                size_t i1 = ((size_t)(row0 + 8) * N + col) >> 1;
                split2(v10, v11, h, l);  Chi[i1] = h;  Clo[i1] = l;
            }
        }
    }
}

// ---------------------------------------------------------------------------
// Tensor-core flash attention, bf16x3 (unchanged from R5; writes split planes)
// ---------------------------------------------------------------------------
#define KSTR 36
#define VSTR 72

__global__ __launch_bounds__(256)
void flash_bf16x3(const uint32_t* __restrict__ qh,
                  const uint32_t* __restrict__ ql,
                  uint32_t* __restrict__ aH, uint32_t* __restrict__ aL)
{
    __shared__ uint32_t Ksh[64 * KSTR], Ksl[64 * KSTR];
    __shared__ uint32_t Vsh[32 * VSTR], Vsl[32 * VSTR];

    const int qbx = blockIdx.x;
    const int h   = blockIdx.y;
    const int b   = blockIdx.z;

    const int tid  = threadIdx.x;
    const int wid  = tid >> 5;
    const int lane = tid & 31;
    const int g = lane >> 2;
    const int t = lane & 3;

    const int qoff = h * 32;
    const int koff = 512 + h * 32;
    const int voff = 1024 + h * 32;

    const int wq = qbx * 128 + wid * 16;
    const size_t rowA = (size_t)(b * SEQ + wq + g) * LD32;
    const size_t rowB = rowA + 8 * LD32;

    uint32_t qfh[4][4], qfl[4][4];
#pragma unroll
    for (int s = 0; s < 4; s++) {
        qfh[s][0] = qh[rowA + qoff + s * 8 + t];
        qfh[s][1] = qh[rowB + qoff + s * 8 + t];
        qfh[s][2] = qh[rowA + qoff + s * 8 + t + 4];
        qfh[s][3] = qh[rowB + qoff + s * 8 + t + 4];
        qfl[s][0] = ql[rowA + qoff + s * 8 + t];
        qfl[s][1] = ql[rowB + qoff + s * 8 + t];
        qfl[s][2] = ql[rowA + qoff + s * 8 + t + 4];
        qfl[s][3] = ql[rowB + qoff + s * 8 + t + 4];
    }

    float oa[8][4];
#pragma unroll
    for (int nt = 0; nt < 8; nt++)
#pragma unroll
        for (int r = 0; r < 4; r++) oa[nt][r] = 0.0f;
    float m0 = -1e30f, m1 = -1e30f, l0 = 0.0f, l1 = 0.0f;

    const int r0g = wq + g;
    const int r1g = wq + g + 8;
    const int nblocks = 2 * qbx + 2;

    for (int jb = 0; jb < nblocks; jb++) {
        __syncthreads();
#pragma unroll
        for (int i = 0; i < 8; i++) {
            int idx = tid + i * 256;
            int tok = idx >> 5, dp = idx & 31;
            size_t gi = (size_t)(b * SEQ + jb * 64 + tok) * LD32 + koff + dp;
            Ksh[tok * KSTR + dp] = qh[gi];
            Ksl[tok * KSTR + dp] = ql[gi];
        }
#pragma unroll
        for (int i = 0; i < 4; i++) {
            int idx = tid + i * 256;
            int r = idx >> 5, j = idx & 31;
            size_t g0 = (size_t)(b * SEQ + jb * 64 + 2 * r) * LD32 + voff + j;
            uint32_t a0 = qh[g0], b0 = qh[g0 + LD32];
            Vsh[r * VSTR + 2 * j]     = __byte_perm(a0, b0, 0x5410);
            Vsh[r * VSTR + 2 * j + 1] = __byte_perm(a0, b0, 0x7632);
            uint32_t a1 = ql[g0], b1 = ql[g0 + LD32];
            Vsl[r * VSTR + 2 * j]     = __byte_perm(a1, b1, 0x5410);
            Vsl[r * VSTR + 2 * j + 1] = __byte_perm(a1, b1, 0x7632);
        }
        __syncthreads();

        if (jb * 64 > wq + 15) continue;

        float sc[8][4];
#pragma unroll
        for (int nt = 0; nt < 8; nt++)
#pragma unroll
            for (int r = 0; r < 4; r++) sc[nt][r] = 0.0f;

#pragma unroll
        for (int s = 0; s < 4; s++) {
#pragma unroll
            for (int nt = 0; nt < 8; nt++) {
                const int tok = nt * 8 + g;
                uint32_t kh0 = Ksh[tok * KSTR + s * 8 + t];
                uint32_t kh1 = Ksh[tok * KSTR + s * 8 + t + 4];
                uint32_t kl0 = Ksl[tok * KSTR + s * 8 + t];
                uint32_t kl1 = Ksl[tok * KSTR + s * 8 + t + 4];
                mma_bf16(sc[nt], qfh[s][0], qfh[s][1], qfh[s][2], qfh[s][3], kh0, kh1);
                mma_bf16(sc[nt], qfh[s][0], qfh[s][1], qfh[s][2], qfh[s][3], kl0, kl1);
                mma_bf16(sc[nt], qfl[s][0], qfl[s][1], qfl[s][2], qfl[s][3], kh0, kh1);
            }
        }

        if (jb * 64 + 63 > wq) {
#pragma unroll
            for (int nt = 0; nt < 8; nt++) {
                int c = jb * 64 + nt * 8 + 2 * t;
                if (c > r0g)     sc[nt][0] = -1e30f;
                if (c + 1 > r0g) sc[nt][1] = -1e30f;
                if (c > r1g)     sc[nt][2] = -1e30f;
                if (c + 1 > r1g) sc[nt][3] = -1e30f;
            }
        }

        float mx0 = -1e30f, mx1 = -1e30f;
#pragma unroll
        for (int nt = 0; nt < 8; nt++) {
            mx0 = fmaxf(mx0, fmaxf(sc[nt][0], sc[nt][1]));
            mx1 = fmaxf(mx1, fmaxf(sc[nt][2], sc[nt][3]));
        }
#pragma unroll
        for (int off = 1; off <= 2; off <<= 1) {
            mx0 = fmaxf(mx0, __shfl_xor_sync(0xffffffffu, mx0, off));
            mx1 = fmaxf(mx1, __shfl_xor_sync(0xffffffffu, mx1, off));
        }
        float mn0 = fmaxf(m0, mx0), mn1 = fmaxf(m1, mx1);
        float corr0 = __expf(m0 - mn0), corr1 = __expf(m1 - mn1);
        float s0 = 0.0f, s1 = 0.0f;
#pragma unroll
        for (int nt = 0; nt < 8; nt++) {
            sc[nt][0] = __expf(sc[nt][0] - mn0);
            sc[nt][1] = __expf(sc[nt][1] - mn0);
            sc[nt][2] = __expf(sc[nt][2] - mn1);
            sc[nt][3] = __expf(sc[nt][3] - mn1);
            s0 += sc[nt][0] + sc[nt][1];
            s1 += sc[nt][2] + sc[nt][3];
        }
#pragma unroll
        for (int off = 1; off <= 2; off <<= 1) {
            s0 += __shfl_xor_sync(0xffffffffu, s0, off);
            s1 += __shfl_xor_sync(0xffffffffu, s1, off);
        }
        l0 = l0 * corr0 + s0;  m0 = mn0;
        l1 = l1 * corr1 + s1;  m1 = mn1;
#pragma unroll
        for (int nt = 0; nt < 8; nt++) {
            oa[nt][0] *= corr0;  oa[nt][1] *= corr0;
            oa[nt][2] *= corr1;  oa[nt][3] *= corr1;
        }

#pragma unroll
        for (int s = 0; s < 4; s++) {
            uint32_t ph[4], pl[4];
            split2(sc[2 * s][0],     sc[2 * s][1],     ph[0], pl[0]);
            split2(sc[2 * s][2],     sc[2 * s][3],     ph[1], pl[1]);
            split2(sc[2 * s + 1][0], sc[2 * s + 1][1], ph[2], pl[2]);
            split2(sc[2 * s + 1][2], sc[2 * s + 1][3], ph[3], pl[3]);
#pragma unroll
            for (int nt = 0; nt < 8; nt++) {
                const int d = nt * 8 + g;
                uint32_t vh0 = Vsh[(s * 8 + t) * VSTR + d];
                uint32_t vh1 = Vsh[(s * 8 + t + 4) * VSTR + d];
                uint32_t vl0 = Vsl[(s * 8 + t) * VSTR + d];
                uint32_t vl1 = Vsl[(s * 8 + t + 4) * VSTR + d];
                mma_bf16(oa[nt], ph[0], ph[1], ph[2], ph[3], vh0, vh1);
                mma_bf16(oa[nt], ph[0], ph[1], ph[2], ph[3], vl0, vl1);
                mma_bf16(oa[nt], pl[0], pl[1], pl[2], pl[3], vh0, vh1);
            }
        }
    }

    const float inv0 = 1.0f / l0, inv1 = 1.0f / l1;
    const size_t o0 = (size_t)(b * SEQ + r0g) * 512 + h * 32;
    const size_t o1 = (size_t)(b * SEQ + r1g) * 512 + h * 32;
#pragma unroll
    for (int nt = 0; nt < 8; nt++) {
        const int dp = nt * 4 + t;
        uint32_t h0, l0u, h1, l1u;
        split2(oa[nt][0] * inv0, oa[nt][1] * inv0, h0, l0u);
        split2(oa[nt][2] * inv1, oa[nt][3] * inv1, h1, l1u);
        aH[o0 + dp] = h0;  aL[o0 + dp] = l0u;
        aH[o1 + dp] = h1;  aL[o1 + dp] = l1u;
    }
}

// ---------------------------------------------------------------------------
// Launch
// ---------------------------------------------------------------------------
extern "C" void kernel_launch(void* const* d_in, const int* in_sizes, int n_in,
                              void* d_out, int out_size)
{
    const float* hidden = (const float*)d_in[0];
    const float* w_attn = (const float*)d_in[1];
    const float* b_attn = (const float*)d_in[2];
    const float* w_proj = (const float*)d_in[3];
    const float* b_proj = (const float*)d_in[4];
    float* out = (float*)d_out;

    uint32_t *qh, *ql, *hh, *hl, *wh, *wl, *ph, *pl, *ah, *al;
    cudaGetSymbolAddress((void**)&qh, g_qh);
    cudaGetSymbolAddress((void**)&ql, g_ql);
    cudaGetSymbolAddress((void**)&hh, g_hh);
    cudaGetSymbolAddress((void**)&hl, g_hl);
    cudaGetSymbolAddress((void**)&wh, g_wh);
    cudaGetSymbolAddress((void**)&wl, g_wl);
    cudaGetSymbolAddress((void**)&ph, g_ph);
    cudaGetSymbolAddress((void**)&pl, g_pl);
    cudaGetSymbolAddress((void**)&ah, g_ah);
    cudaGetSymbolAddress((void**)&al, g_al);

    static bool attr_set = false;
    if (!attr_set) {
        cudaFuncSetAttribute(gemm_planes,
                             cudaFuncAttributeMaxDynamicSharedMemorySize, GEMM_SMEM);
        attr_set = true;
    }

    // 0) prep: split hidden; transpose+split weights
    {
        const int n = M_TOK * 512;
        split_pairs<<<(n + 255) / 256, 256>>>((const float2*)hidden, hh, hl, n);
        dim3 gw(QKV_N / 32, HIDDEN / 64);
        transpose_split<<<gw, 256>>>(w_attn, wh, wl, HIDDEN, QKV_N);
        dim3 gp(HIDDEN / 32, HIDDEN / 64);
        transpose_split<<<gp, 256>>>(w_proj, ph, pl, HIDDEN, HIDDEN);
    }
    // 1) QKV projection -> split qkv planes
    {
        dim3 grid(QKV_N / 128, M_TOK / 128);
        gemm_planes<<<grid, 256, GEMM_SMEM>>>(hh, hl, wh, wl, b_attn,
                                              nullptr, qh, ql,
                                              M_TOK, QKV_N, HIDDEN / 2, 1);
    }
    // 2) flash attention -> split attn planes
    {
        dim3 grid(SEQ / 128, NHEAD, BATCH);
        flash_bf16x3<<<grid, 256>>>(qh, ql, ah, al);
    }
    // 3) output projection -> fp32 out
    {
        dim3 grid(HIDDEN / 128, M_TOK / 128);
        gemm_planes<<<grid, 256, GEMM_SMEM>>>(ah, al, ph, pl, b_proj,
                                              out, nullptr, nullptr,
                                              M_TOK, HIDDEN, HIDDEN / 2, 0);
    }
}

// round 7
// speedup vs baseline: 1.1151x; 1.0666x over previous
#include <cuda_runtime.h>
#include <cuda_bf16.h>
#include <math.h>
#include <stdint.h>

// ---------------------------------------------------------------------------
// Problem constants
// ---------------------------------------------------------------------------
#define BATCH 2
#define SEQ 2048
#define HIDDEN 1024
#define NHEAD 16
#define HDIM 64
#define M_TOK (BATCH * SEQ)          // 4096
#define QKV_N (3 * HIDDEN)           // 3072
#define LD32 (QKV_N / 2)             // 1536 u32 per token row (qkv planes)

// Scratch (__device__ globals per allocation rules)
__device__ uint32_t g_qh[(size_t)M_TOK * LD32];      // qkv hi plane
__device__ uint32_t g_ql[(size_t)M_TOK * LD32];      // qkv lo plane
__device__ float    g_attn[(size_t)M_TOK * HIDDEN];  // attention output fp32
__device__ int8_t   g_a1[(size_t)M_TOK * HIDDEN];    // attn digit1
__device__ int8_t   g_a2[(size_t)M_TOK * HIDDEN];    // attn digit2
__device__ int8_t   g_w1[(size_t)HIDDEN * HIDDEN];   // w_proj^T digit1 [n][k]
__device__ int8_t   g_w2[(size_t)HIDDEN * HIDDEN];   // w_proj^T digit2
__device__ unsigned g_maxA;                          // max|attn| (float bits)
__device__ unsigned g_maxW;                          // max|w_proj|

// ---------------------------------------------------------------------------
// Helpers
// ---------------------------------------------------------------------------
__device__ __forceinline__ void split2(float x, float y,
                                       uint32_t& hi, uint32_t& lo) {
    __nv_bfloat162 h = __floats2bfloat162_rn(x, y);
    float2 hf = __bfloat1622float2(h);
    __nv_bfloat162 l = __floats2bfloat162_rn(x - hf.x, y - hf.y);
    hi = *reinterpret_cast<uint32_t*>(&h);
    lo = *reinterpret_cast<uint32_t*>(&l);
}

__device__ __forceinline__ void mma_bf16(float* c, uint32_t a0, uint32_t a1,
                                         uint32_t a2, uint32_t a3,
                                         uint32_t b0, uint32_t b1) {
    asm volatile(
        "mma.sync.aligned.m16n8k16.row.col.f32.bf16.bf16.f32 "
        "{%0,%1,%2,%3}, {%4,%5,%6,%7}, {%8,%9}, {%0,%1,%2,%3};"
        : "+f"(c[0]), "+f"(c[1]), "+f"(c[2]), "+f"(c[3])
        : "r"(a0), "r"(a1), "r"(a2), "r"(a3), "r"(b0), "r"(b1));
}

__device__ __forceinline__ void mma_s8(int* c, uint32_t a0, uint32_t a1,
                                       uint32_t a2, uint32_t a3,
                                       uint32_t b0, uint32_t b1) {
    asm volatile(
        "mma.sync.aligned.m16n8k32.row.col.s32.s8.s8.s32 "
        "{%0,%1,%2,%3}, {%4,%5,%6,%7}, {%8,%9}, {%0,%1,%2,%3};"
        : "+r"(c[0]), "+r"(c[1]), "+r"(c[2]), "+r"(c[3])
        : "r"(a0), "r"(a1), "r"(a2), "r"(a3), "r"(b0), "r"(b1));
}

__device__ __forceinline__ void ldsm4(uint32_t& r0, uint32_t& r1,
                                      uint32_t& r2, uint32_t& r3, uint32_t a) {
    asm volatile("ldmatrix.sync.aligned.m8n8.x4.shared.b16 {%0,%1,%2,%3}, [%4];"
                 : "=r"(r0), "=r"(r1), "=r"(r2), "=r"(r3) : "r"(a));
}

__device__ __forceinline__ void cp16(uint32_t smem, const void* gmem) {
    asm volatile("cp.async.ca.shared.global [%0], [%1], 16;"
                 :: "r"(smem), "l"(gmem));
}
#define CP_COMMIT() asm volatile("cp.async.commit_group;" ::: "memory")
#define CP_WAIT(n)  asm volatile("cp.async.wait_group %0;" :: "n"(n) : "memory")

// quantize x (|x| <= max) to q1*256 + q2 with S = 32512/max
__device__ __forceinline__ void quant2(float x, float S, int8_t& d1, int8_t& d2) {
    int q = __float2int_rn(x * S);
    int q1 = (q + 128) >> 8;
    d1 = (int8_t)q1;
    d2 = (int8_t)(q - (q1 << 8));
}

// ---------------------------------------------------------------------------
// max-abs reduction (atomicMax on positive float bits)
// ---------------------------------------------------------------------------
__global__ __launch_bounds__(256)
void maxabs_kernel(const float* __restrict__ x, int n, unsigned* __restrict__ out)
{
    float m = 0.0f;
    for (int i = blockIdx.x * 256 + threadIdx.x; i < n; i += gridDim.x * 256)
        m = fmaxf(m, fabsf(x[i]));
#pragma unroll
    for (int off = 16; off >= 1; off >>= 1)
        m = fmaxf(m, __shfl_xor_sync(0xffffffffu, m, off));
    if ((threadIdx.x & 31) == 0)
        atomicMax(out, __float_as_uint(m));
}

// ---------------------------------------------------------------------------
// quantize attn fp32 [M][K] -> digit planes
// ---------------------------------------------------------------------------
__global__ __launch_bounds__(256)
void quant_attn_kernel(const float* __restrict__ x,
                       int8_t* __restrict__ d1, int8_t* __restrict__ d2, int n)
{
    const float maxv = fmaxf(__uint_as_float(g_maxA), 1e-30f);
    const float S = 32512.0f / maxv;
    int i = blockIdx.x * 256 + threadIdx.x;
    if (i < n) quant2(x[i], S, d1[i], d2[i]);
}

// ---------------------------------------------------------------------------
// transpose + quantize  W[K][N] -> digit planes [N][K]
// ---------------------------------------------------------------------------
__global__ __launch_bounds__(256)
void transpose_quant_kernel(const float* __restrict__ W,
                            int8_t* __restrict__ d1, int8_t* __restrict__ d2,
                            int K, int N)
{
    __shared__ float s[64][33];
    const int tid = threadIdx.x;
    const int k0 = blockIdx.y * 64;
    const int n0 = blockIdx.x * 32;
    const float maxv = fmaxf(__uint_as_float(g_maxW), 1e-30f);
    const float S = 32512.0f / maxv;

#pragma unroll
    for (int i = 0; i < 8; i++) {
        int idx = tid + i * 256;
        int nl = idx & 31;
        int kl = idx >> 5;
        s[kl][nl] = W[(size_t)(k0 + kl) * N + n0 + nl];
    }
    __syncthreads();

#pragma unroll
    for (int i = 0; i < 8; i++) {
        int idx = tid + i * 256;
        int kl = idx & 63;
        int nl = idx >> 6;               // 0..31
        size_t o = (size_t)(n0 + nl) * K + k0 + kl;
        quant2(s[kl][nl], S, d1[o], d2[o]);
    }
}

// ---------------------------------------------------------------------------
// bf16x3 GEMM + bias (R3 kernel, verbatim): C = A[M,K] @ B[K,N] + bias
// mode 0: fp32 C. mode 1: split bf16 planes Chi/Clo.
// ---------------------------------------------------------------------------
#define GASTR 12
#define GBSTR 136

__global__ __launch_bounds__(256)
void gemm_bf16x3(const float* __restrict__ A, const float* __restrict__ B,
                 const float* __restrict__ bias,
                 float* __restrict__ Cf,
                 uint32_t* __restrict__ Chi, uint32_t* __restrict__ Clo,
                 int M, int N, int K, int mode)
{
    __shared__ uint32_t Ah[2][128 * GASTR], Al[2][128 * GASTR];
    __shared__ uint32_t Bh[2][8 * GBSTR],  Bl[2][8 * GBSTR];

    const int tid  = threadIdx.x;
    const int warp = tid >> 5;
    const int lane = tid & 31;
    const int g = lane >> 2;
    const int t = lane & 3;
    const int wm = (warp >> 2) * 64;
    const int wn = (warp & 3) * 32;
    const int brow = blockIdx.y * 128;
    const int bcol = blockIdx.x * 128;

    float acc[4][4][4];
#pragma unroll
    for (int mt = 0; mt < 4; mt++)
#pragma unroll
        for (int nt = 0; nt < 4; nt++)
#pragma unroll
            for (int r = 0; r < 4; r++) acc[mt][nt][r] = 0.0f;

    const int am[2] = { (tid + 0) >> 2, (tid + 256) >> 2 };
    const int aq[2] = { (tid + 0) & 3,  (tid + 256) & 3 };
    const int bkp   = tid >> 5;
    const int bn0   = (tid & 31) * 4;

    float4 pa[2], pb0, pb1;

    auto prefetch = [&](int k0) {
#pragma unroll
        for (int it = 0; it < 2; it++)
            pa[it] = *(const float4*)(A + (size_t)(brow + am[it]) * K + k0 + aq[it] * 4);
        pb0 = *(const float4*)(B + (size_t)(k0 + 2 * bkp) * N + bcol + bn0);
        pb1 = *(const float4*)(B + (size_t)(k0 + 2 * bkp + 1) * N + bcol + bn0);
    };
    auto stage = [&](int buf) {
#pragma unroll
        for (int it = 0; it < 2; it++) {
            uint32_t h0, l0, h1, l1;
            split2(pa[it].x, pa[it].y, h0, l0);
            split2(pa[it].z, pa[it].w, h1, l1);
            int base = am[it] * GASTR + aq[it] * 2;
            Ah[buf][base] = h0;  Ah[buf][base + 1] = h1;
            Al[buf][base] = l0;  Al[buf][base + 1] = l1;
        }
        uint32_t h[4], l[4];
        split2(pb0.x, pb1.x, h[0], l[0]);
        split2(pb0.y, pb1.y, h[1], l[1]);
        split2(pb0.z, pb1.z, h[2], l[2]);
        split2(pb0.w, pb1.w, h[3], l[3]);
        *(uint4*)&Bh[buf][bkp * GBSTR + bn0] = make_uint4(h[0], h[1], h[2], h[3]);
        *(uint4*)&Bl[buf][bkp * GBSTR + bn0] = make_uint4(l[0], l[1], l[2], l[3]);
    };

    prefetch(0);
    stage(0);
    __syncthreads();

    int buf = 0;
    for (int k0 = 0; k0 < K; k0 += 16) {
        const bool has_next = (k0 + 16) < K;
        if (has_next) prefetch(k0 + 16);

        uint32_t bh[4][2], bl[4][2];
#pragma unroll
        for (int nt = 0; nt < 4; nt++) {
            const int col = wn + nt * 8 + g;
            bh[nt][0] = Bh[buf][t * GBSTR + col];
            bh[nt][1] = Bh[buf][(t + 4) * GBSTR + col];
            bl[nt][0] = Bl[buf][t * GBSTR + col];
            bl[nt][1] = Bl[buf][(t + 4) * GBSTR + col];
        }
#pragma unroll
        for (int mt = 0; mt < 4; mt++) {
            const int r = wm + mt * 16 + g;
            uint32_t ah0 = Ah[buf][r * GASTR + t];
            uint32_t ah1 = Ah[buf][(r + 8) * GASTR + t];
            uint32_t ah2 = Ah[buf][r * GASTR + t + 4];
            uint32_t ah3 = Ah[buf][(r + 8) * GASTR + t + 4];
            uint32_t al0 = Al[buf][r * GASTR + t];
            uint32_t al1 = Al[buf][(r + 8) * GASTR + t];
            uint32_t al2 = Al[buf][r * GASTR + t + 4];
            uint32_t al3 = Al[buf][(r + 8) * GASTR + t + 4];
#pragma unroll
            for (int nt = 0; nt < 4; nt++) {
                mma_bf16(acc[mt][nt], ah0, ah1, ah2, ah3, bh[nt][0], bh[nt][1]);
                mma_bf16(acc[mt][nt], ah0, ah1, ah2, ah3, bl[nt][0], bl[nt][1]);
                mma_bf16(acc[mt][nt], al0, al1, al2, al3, bh[nt][0], bh[nt][1]);
            }
        }

        if (has_next) {
            stage(buf ^ 1);
            __syncthreads();
            buf ^= 1;
        }
    }

#pragma unroll
    for (int nt = 0; nt < 4; nt++) {
        const int col = bcol + wn + nt * 8 + 2 * t;
        const float2 bv = *(const float2*)(bias + col);
#pragma unroll
        for (int mt = 0; mt < 4; mt++) {
            const int row0 = brow + wm + mt * 16 + g;
            float v00 = acc[mt][nt][0] + bv.x, v01 = acc[mt][nt][1] + bv.y;
            float v10 = acc[mt][nt][2] + bv.x, v11 = acc[mt][nt][3] + bv.y;
            if (mode == 0) {
                *(float2*)(Cf + (size_t)row0 * N + col)       = make_float2(v00, v01);
                *(float2*)(Cf + (size_t)(row0 + 8) * N + col) = make_float2(v10, v11);
            } else {
                uint32_t h, l;
                size_t i0 = ((size_t)row0 * N + col) >> 1;
                split2(v00, v01, h, l);  Chi[i0] = h;  Clo[i0] = l;
                size_t i1 = ((size_t)(row0 + 8) * N + col) >> 1;
                split2(v10, v11, h, l);  Chi[i1] = h;  Clo[i1] = l;
            }
        }
    }
}

// ---------------------------------------------------------------------------
// int8 2-digit GEMM + bias:  out[M,N] = dequant(A1,A2 @ W1,W2) + bias
// A digits: [M][K] int8; W digits: [N][K] int8. CTA 128x64, 8 warps (4m x 2n),
// warp tile 32x32. k-chunk 32. cp.async 4-stage. Rows padded to 48B in smem.
// C = (65536*G1 + 256*G2) * (maxA*maxW/32512^2) + bias
// ---------------------------------------------------------------------------
#define IA_PL 6144                   // 128 rows * 48B
#define IB_PL 3072                   // 64 rows * 48B
#define ISTG (2 * IA_PL + 2 * IB_PL) // 18432
#define INST 4
#define INT8_SMEM (INST * ISTG)      // 73728

__global__ __launch_bounds__(256, 2)
void gemm_int8(const int8_t* __restrict__ A1, const int8_t* __restrict__ A2,
               const int8_t* __restrict__ W1, const int8_t* __restrict__ W2,
               const float* __restrict__ bias, float* __restrict__ C,
               int M, int N, int K)
{
    extern __shared__ uint32_t smem[];
    const uint32_t sb = (uint32_t)__cvta_generic_to_shared(smem);

    const int tid  = threadIdx.x;
    const int warp = tid >> 5;
    const int lane = tid & 31;
    const int g = lane >> 2;
    const int t = lane & 3;
    const int wm = (warp >> 1) * 32;
    const int wn = (warp & 1) * 32;
    const int brow = blockIdx.y * 128;
    const int bcol = blockIdx.x * 64;

    // cp.async mapping
    const int arow = tid >> 1, ahalf = tid & 1;
    const int wrow = tid >> 2, whalf = (tid >> 1) & 1, wpl = tid & 1;
    const int8_t* gA[2] = { A1 + (size_t)(brow + arow) * K + ahalf * 16,
                            A2 + (size_t)(brow + arow) * K + ahalf * 16 };
    const int8_t* gW   = (wpl ? W2 : W1) + (size_t)(bcol + wrow) * K + whalf * 16;

    auto issue_chunk = [&](int c) {
        const uint32_t base = sb + (uint32_t)((c & (INST - 1)) * ISTG);
        const int k0 = c * 32;
        cp16(base + 0 * IA_PL + arow * 48 + ahalf * 16, gA[0] + k0);
        cp16(base + 1 * IA_PL + arow * 48 + ahalf * 16, gA[1] + k0);
        cp16(base + 2 * IA_PL + wpl * IB_PL + wrow * 48 + whalf * 16, gW + k0);
        CP_COMMIT();
    };

    // ldmatrix lane addressing (rows padded to 48B)
    const int laA = (lane & 7) + ((lane >> 3) & 1) * 8;
    const uint32_t kaA = (uint32_t)(((lane >> 4) & 1) * 16);
    const int laB = (lane & 7) + ((lane >> 4) & 1) * 8;
    const uint32_t kaB = (uint32_t)(((lane >> 3) & 1) * 16);

    int acc1[2][4][4], acc2[2][4][4];
#pragma unroll
    for (int mt = 0; mt < 2; mt++)
#pragma unroll
        for (int nt = 0; nt < 4; nt++)
#pragma unroll
            for (int r = 0; r < 4; r++) { acc1[mt][nt][r] = 0; acc2[mt][nt][r] = 0; }

    const int NC = K / 32;
#pragma unroll
    for (int s = 0; s < INST - 1; s++) issue_chunk(s);

    for (int c = 0; c < NC; c++) {
        CP_WAIT(INST - 2);
        __syncthreads();
        if (c + INST - 1 < NC) issue_chunk(c + INST - 1);

        const uint32_t base = sb + (uint32_t)((c & (INST - 1)) * ISTG);
        // B fragments: 2 planes x 2 ldsm.x4 (each covers 2 n-tiles)
        uint32_t b1[4][2], b2[4][2];
#pragma unroll
        for (int np = 0; np < 2; np++) {
            const uint32_t ro = (uint32_t)((wn + np * 16 + laB) * 48) + kaB;
            ldsm4(b1[2 * np][0], b1[2 * np][1], b1[2 * np + 1][0], b1[2 * np + 1][1],
                  base + 2 * IA_PL + ro);
            ldsm4(b2[2 * np][0], b2[2 * np][1], b2[2 * np + 1][0], b2[2 * np + 1][1],
                  base + 2 * IA_PL + IB_PL + ro);
        }
#pragma unroll
        for (int mt = 0; mt < 2; mt++) {
            const uint32_t ro = (uint32_t)((wm + mt * 16 + laA) * 48) + kaA;
            uint32_t a1f[4], a2f[4];
            ldsm4(a1f[0], a1f[1], a1f[2], a1f[3], base + ro);
            ldsm4(a2f[0], a2f[1], a2f[2], a2f[3], base + IA_PL + ro);
#pragma unroll
            for (int nt = 0; nt < 4; nt++) {
                mma_s8(acc1[mt][nt], a1f[0], a1f[1], a1f[2], a1f[3],
                       b1[nt][0], b1[nt][1]);
                mma_s8(acc2[mt][nt], a1f[0], a1f[1], a1f[2], a1f[3],
                       b2[nt][0], b2[nt][1]);
                mma_s8(acc2[mt][nt], a2f[0], a2f[1], a2f[2], a2f[3],
                       b1[nt][0], b1[nt][1]);
            }
        }
    }

    const float maxA = fmaxf(__uint_as_float(g_maxA), 1e-30f);
    const float maxW = fmaxf(__uint_as_float(g_maxW), 1e-30f);
    const float inv = (maxA * maxW) / (32512.0f * 32512.0f);

#pragma unroll
    for (int nt = 0; nt < 4; nt++) {
        const int col = bcol + wn + nt * 8 + 2 * t;
        const float2 bv = *(const float2*)(bias + col);
#pragma unroll
        for (int mt = 0; mt < 2; mt++) {
            const int row0 = brow + wm + mt * 16 + g;
            float2 o0, o1;
            o0.x = (65536.0f * (float)acc1[mt][nt][0] + 256.0f * (float)acc2[mt][nt][0]) * inv + bv.x;
            o0.y = (65536.0f * (float)acc1[mt][nt][1] + 256.0f * (float)acc2[mt][nt][1]) * inv + bv.y;
            o1.x = (65536.0f * (float)acc1[mt][nt][2] + 256.0f * (float)acc2[mt][nt][2]) * inv + bv.x;
            o1.y = (65536.0f * (float)acc1[mt][nt][3] + 256.0f * (float)acc2[mt][nt][3]) * inv + bv.y;
            *(float2*)(C + (size_t)row0 * N + col)       = o0;
            *(float2*)(C + (size_t)(row0 + 8) * N + col) = o1;
        }
    }
}

// ---------------------------------------------------------------------------
// Tensor-core flash attention, bf16x3 (R3 version; qbx reversed for balance)
// ---------------------------------------------------------------------------
#define KSTR 36
#define VSTR 72

__global__ __launch_bounds__(256)
void flash_bf16x3(const uint32_t* __restrict__ qh,
                  const uint32_t* __restrict__ ql,
                  float* __restrict__ out)
{
    __shared__ uint32_t Ksh[64 * KSTR], Ksl[64 * KSTR];
    __shared__ uint32_t Vsh[32 * VSTR], Vsl[32 * VSTR];

    const int qbx = gridDim.x - 1 - blockIdx.x;   // big tiles first
    const int h   = blockIdx.y;
    const int b   = blockIdx.z;

    const int tid  = threadIdx.x;
    const int wid  = tid >> 5;
    const int lane = tid & 31;
    const int g = lane >> 2;
    const int t = lane & 3;

    const int qoff = h * 32;
    const int koff = 512 + h * 32;
    const int voff = 1024 + h * 32;

    const int wq = qbx * 128 + wid * 16;
    const size_t rowA = (size_t)(b * SEQ + wq + g) * LD32;
    const size_t rowB = rowA + 8 * LD32;

    uint32_t qfh[4][4], qfl[4][4];
#pragma unroll
    for (int s = 0; s < 4; s++) {
        qfh[s][0] = qh[rowA + qoff + s * 8 + t];
        qfh[s][1] = qh[rowB + qoff + s * 8 + t];
        qfh[s][2] = qh[rowA + qoff + s * 8 + t + 4];
        qfh[s][3] = qh[rowB + qoff + s * 8 + t + 4];
        qfl[s][0] = ql[rowA + qoff + s * 8 + t];
        qfl[s][1] = ql[rowB + qoff + s * 8 + t];
        qfl[s][2] = ql[rowA + qoff + s * 8 + t + 4];
        qfl[s][3] = ql[rowB + qoff + s * 8 + t + 4];
    }

    float oa[8][4];
#pragma unroll
    for (int nt = 0; nt < 8; nt++)
#pragma unroll
        for (int r = 0; r < 4; r++) oa[nt][r] = 0.0f;
    float m0 = -1e30f, m1 = -1e30f, l0 = 0.0f, l1 = 0.0f;

    const int r0g = wq + g;
    const int r1g = wq + g + 8;
    const int nblocks = 2 * qbx + 2;

    for (int jb = 0; jb < nblocks; jb++) {
        __syncthreads();
#pragma unroll
        for (int i = 0; i < 8; i++) {
            int idx = tid + i * 256;
            int tok = idx >> 5, dp = idx & 31;
            size_t gi = (size_t)(b * SEQ + jb * 64 + tok) * LD32 + koff + dp;
            Ksh[tok * KSTR + dp] = qh[gi];
            Ksl[tok * KSTR + dp] = ql[gi];
        }
#pragma unroll
        for (int i = 0; i < 4; i++) {
            int idx = tid + i * 256;
            int r = idx >> 5, j = idx & 31;
            size_t g0 = (size_t)(b * SEQ + jb * 64 + 2 * r) * LD32 + voff + j;
            uint32_t a0 = qh[g0], b0 = qh[g0 + LD32];
            Vsh[r * VSTR + 2 * j]     = __byte_perm(a0, b0, 0x5410);
            Vsh[r * VSTR + 2 * j + 1] = __byte_perm(a0, b0, 0x7632);
            uint32_t a1 = ql[g0], b1 = ql[g0 + LD32];
            Vsl[r * VSTR + 2 * j]     = __byte_perm(a1, b1, 0x5410);
            Vsl[r * VSTR + 2 * j + 1] = __byte_perm(a1, b1, 0x7632);
        }
        __syncthreads();

        if (jb * 64 > wq + 15) continue;

        float sc[8][4];
#pragma unroll
        for (int nt = 0; nt < 8; nt++)
#pragma unroll
            for (int r = 0; r < 4; r++) sc[nt][r] = 0.0f;

#pragma unroll
        for (int s = 0; s < 4; s++) {
#pragma unroll
            for (int nt = 0; nt < 8; nt++) {
                const int tok = nt * 8 + g;
                uint32_t kh0 = Ksh[tok * KSTR + s * 8 + t];
                uint32_t kh1 = Ksh[tok * KSTR + s * 8 + t + 4];
                uint32_t kl0 = Ksl[tok * KSTR + s * 8 + t];
                uint32_t kl1 = Ksl[tok * KSTR + s * 8 + t + 4];
                mma_bf16(sc[nt], qfh[s][0], qfh[s][1], qfh[s][2], qfh[s][3], kh0, kh1);
                mma_bf16(sc[nt], qfh[s][0], qfh[s][1], qfh[s][2], qfh[s][3], kl0, kl1);
                mma_bf16(sc[nt], qfl[s][0], qfl[s][1], qfl[s][2], qfl[s][3], kh0, kh1);
            }
        }

        if (jb * 64 + 63 > wq) {
#pragma unroll
            for (int nt = 0; nt < 8; nt++) {
                int c = jb * 64 + nt * 8 + 2 * t;
                if (c > r0g)     sc[nt][0] = -1e30f;
                if (c + 1 > r0g) sc[nt][1] = -1e30f;
                if (c > r1g)     sc[nt][2] = -1e30f;
                if (c + 1 > r1g) sc[nt][3] = -1e30f;
            }
        }

        float mx0 = -1e30f, mx1 = -1e30f;
#pragma unroll
        for (int nt = 0; nt < 8; nt++) {
            mx0 = fmaxf(mx0, fmaxf(sc[nt][0], sc[nt][1]));
            mx1 = fmaxf(mx1, fmaxf(sc[nt][2], sc[nt][3]));
        }
#pragma unroll
        for (int off = 1; off <= 2; off <<= 1) {
            mx0 = fmaxf(mx0, __shfl_xor_sync(0xffffffffu, mx0, off));
            mx1 = fmaxf(mx1, __shfl_xor_sync(0xffffffffu, mx1, off));
        }
        float mn0 = fmaxf(m0, mx0), mn1 = fmaxf(m1, mx1);
        float corr0 = __expf(m0 - mn0), corr1 = __expf(m1 - mn1);
        float s0 = 0.0f, s1 = 0.0f;
#pragma unroll
        for (int nt = 0; nt < 8; nt++) {
            sc[nt][0] = __expf(sc[nt][0] - mn0);
            sc[nt][1] = __expf(sc[nt][1] - mn0);
            sc[nt][2] = __expf(sc[nt][2] - mn1);
            sc[nt][3] = __expf(sc[nt][3] - mn1);
            s0 += sc[nt][0] + sc[nt][1];
            s1 += sc[nt][2] + sc[nt][3];
        }
#pragma unroll
        for (int off = 1; off <= 2; off <<= 1) {
            s0 += __shfl_xor_sync(0xffffffffu, s0, off);
            s1 += __shfl_xor_sync(0xffffffffu, s1, off);
        }
        l0 = l0 * corr0 + s0;  m0 = mn0;
        l1 = l1 * corr1 + s1;  m1 = mn1;
#pragma unroll
        for (int nt = 0; nt < 8; nt++) {
            oa[nt][0] *= corr0;  oa[nt][1] *= corr0;
            oa[nt][2] *= corr1;  oa[nt][3] *= corr1;
        }

#pragma unroll
        for (int s = 0; s < 4; s++) {
            uint32_t ph[4], pl[4];
            split2(sc[2 * s][0],     sc[2 * s][1],     ph[0], pl[0]);
            split2(sc[2 * s][2],     sc[2 * s][3],     ph[1], pl[1]);
            split2(sc[2 * s + 1][0], sc[2 * s + 1][1], ph[2], pl[2]);
            split2(sc[2 * s + 1][2], sc[2 * s + 1][3], ph[3], pl[3]);
#pragma unroll
            for (int nt = 0; nt < 8; nt++) {
                const int d = nt * 8 + g;
                uint32_t vh0 = Vsh[(s * 8 + t) * VSTR + d];
                uint32_t vh1 = Vsh[(s * 8 + t + 4) * VSTR + d];
                uint32_t vl0 = Vsl[(s * 8 + t) * VSTR + d];
                uint32_t vl1 = Vsl[(s * 8 + t + 4) * VSTR + d];
                mma_bf16(oa[nt], ph[0], ph[1], ph[2], ph[3], vh0, vh1);
                mma_bf16(oa[nt], ph[0], ph[1], ph[2], ph[3], vl0, vl1);
                mma_bf16(oa[nt], pl[0], pl[1], pl[2], pl[3], vh0, vh1);
            }
        }
    }

    const float inv0 = 1.0f / l0, inv1 = 1.0f / l1;
    const size_t orow0 = (size_t)(b * SEQ + r0g) * HIDDEN + h * HDIM;
    const size_t orow1 = (size_t)(b * SEQ + r1g) * HIDDEN + h * HDIM;
#pragma unroll
    for (int nt = 0; nt < 8; nt++) {
        const int d = nt * 8 + 2 * t;
        *(float2*)(out + orow0 + d) = make_float2(oa[nt][0] * inv0, oa[nt][1] * inv0);
        *(float2*)(out + orow1 + d) = make_float2(oa[nt][2] * inv1, oa[nt][3] * inv1);
    }
}

// ---------------------------------------------------------------------------
// Launch
// ---------------------------------------------------------------------------
extern "C" void kernel_launch(void* const* d_in, const int* in_sizes, int n_in,
                              void* d_out, int out_size)
{
    const float* hidden = (const float*)d_in[0];
    const float* w_attn = (const float*)d_in[1];
    const float* b_attn = (const float*)d_in[2];
    const float* w_proj = (const float*)d_in[3];
    const float* b_proj = (const float*)d_in[4];
    float* out = (float*)d_out;

    uint32_t *qh, *ql;
    float* attn;
    int8_t *a1, *a2, *w1, *w2;
    unsigned *mA, *mW;
    cudaGetSymbolAddress((void**)&qh, g_qh);
    cudaGetSymbolAddress((void**)&ql, g_ql);
    cudaGetSymbolAddress((void**)&attn, g_attn);
    cudaGetSymbolAddress((void**)&a1, g_a1);
    cudaGetSymbolAddress((void**)&a2, g_a2);
    cudaGetSymbolAddress((void**)&w1, g_w1);
    cudaGetSymbolAddress((void**)&w2, g_w2);
    cudaGetSymbolAddress((void**)&mA, g_maxA);
    cudaGetSymbolAddress((void**)&mW, g_maxW);

    static bool attr_set = false;
    if (!attr_set) {
        cudaFuncSetAttribute(gemm_int8,
                             cudaFuncAttributeMaxDynamicSharedMemorySize, INT8_SMEM);
        attr_set = true;
    }

    // 0) w_proj max + transpose/quantize (independent of main chain)
    maxabs_kernel<<<256, 256>>>(w_proj, HIDDEN * HIDDEN, mW);
    {
        dim3 gp(HIDDEN / 32, HIDDEN / 64);
        transpose_quant_kernel<<<gp, 256>>>(w_proj, w1, w2, HIDDEN, HIDDEN);
    }
    // 1) QKV projection -> split bf16 planes (R3 kernel)
    {
        dim3 grid(QKV_N / 128, M_TOK / 128);
        gemm_bf16x3<<<grid, 256>>>(hidden, w_attn, b_attn,
                                   nullptr, qh, ql,
                                   M_TOK, QKV_N, HIDDEN, 1);
    }
    // 2) flash attention -> fp32 attn
    {
        dim3 grid(SEQ / 128, NHEAD, BATCH);
        flash_bf16x3<<<grid, 256>>>(qh, ql, attn);
    }
    // 3) attn max + quantize to digits
    maxabs_kernel<<<256, 256>>>(attn, M_TOK * HIDDEN, mA);
    {
        const int n = M_TOK * HIDDEN;
        quant_attn_kernel<<<(n + 255) / 256, 256>>>(attn, a1, a2, n);
    }
    // 4) output projection via int8 IMMA
    {
        dim3 grid(HIDDEN / 64, M_TOK / 128);
        gemm_int8<<<grid, 256, INT8_SMEM>>>(a1, a2, w1, w2, b_proj, out,
                                            M_TOK, HIDDEN, HIDDEN);
    }
}

// round 8
// speedup vs baseline: 1.1411x; 1.0233x over previous
#include <cuda_runtime.h>
#include <cuda_bf16.h>
#include <math.h>
#include <stdint.h>

// ---------------------------------------------------------------------------
// Problem constants
// ---------------------------------------------------------------------------
#define BATCH 2
#define SEQ 2048
#define HIDDEN 1024
#define NHEAD 16
#define HDIM 64
#define M_TOK (BATCH * SEQ)          // 4096
#define QKV_N (3 * HIDDEN)           // 3072
#define LD32 (QKV_N / 2)             // 1536 u32 per token row (qkv planes)

// Scratch (__device__ globals per allocation rules)
__device__ uint32_t g_qh[(size_t)M_TOK * LD32];      // qkv hi plane
__device__ uint32_t g_ql[(size_t)M_TOK * LD32];      // qkv lo plane
__device__ float    g_attn[(size_t)M_TOK * HIDDEN];  // attention output fp32

// ---------------------------------------------------------------------------
// Helpers
// ---------------------------------------------------------------------------
__device__ __forceinline__ void split2(float x, float y,
                                       uint32_t& hi, uint32_t& lo) {
    __nv_bfloat162 h = __floats2bfloat162_rn(x, y);
    float2 hf = __bfloat1622float2(h);
    __nv_bfloat162 l = __floats2bfloat162_rn(x - hf.x, y - hf.y);
    hi = *reinterpret_cast<uint32_t*>(&h);
    lo = *reinterpret_cast<uint32_t*>(&l);
}

__device__ __forceinline__ void mma_bf16(float* c, uint32_t a0, uint32_t a1,
                                         uint32_t a2, uint32_t a3,
                                         uint32_t b0, uint32_t b1) {
    asm volatile(
        "mma.sync.aligned.m16n8k16.row.col.f32.bf16.bf16.f32 "
        "{%0,%1,%2,%3}, {%4,%5,%6,%7}, {%8,%9}, {%0,%1,%2,%3};"
        : "+f"(c[0]), "+f"(c[1]), "+f"(c[2]), "+f"(c[3])
        : "r"(a0), "r"(a1), "r"(a2), "r"(a3), "r"(b0), "r"(b1));
}

__device__ __forceinline__ void ldsm4(uint32_t& r0, uint32_t& r1,
                                      uint32_t& r2, uint32_t& r3, uint32_t a) {
    asm volatile("ldmatrix.sync.aligned.m8n8.x4.shared.b16 {%0,%1,%2,%3}, [%4];"
                 : "=r"(r0), "=r"(r1), "=r"(r2), "=r"(r3) : "r"(a));
}

// ---------------------------------------------------------------------------
// bf16x3 GEMM + bias (R3 kernel, verbatim): C = A[M,K] @ B[K,N] + bias
// mode 0: fp32 C. mode 1: split bf16 planes Chi/Clo.
// ---------------------------------------------------------------------------
#define GASTR 12
#define GBSTR 136

__global__ __launch_bounds__(256)
void gemm_bf16x3(const float* __restrict__ A, const float* __restrict__ B,
                 const float* __restrict__ bias,
                 float* __restrict__ Cf,
                 uint32_t* __restrict__ Chi, uint32_t* __restrict__ Clo,
                 int M, int N, int K, int mode)
{
    __shared__ uint32_t Ah[2][128 * GASTR], Al[2][128 * GASTR];
    __shared__ uint32_t Bh[2][8 * GBSTR],  Bl[2][8 * GBSTR];

    const int tid  = threadIdx.x;
    const int warp = tid >> 5;
    const int lane = tid & 31;
    const int g = lane >> 2;
    const int t = lane & 3;
    const int wm = (warp >> 2) * 64;
    const int wn = (warp & 3) * 32;
    const int brow = blockIdx.y * 128;
    const int bcol = blockIdx.x * 128;

    float acc[4][4][4];
#pragma unroll
    for (int mt = 0; mt < 4; mt++)
#pragma unroll
        for (int nt = 0; nt < 4; nt++)
#pragma unroll
            for (int r = 0; r < 4; r++) acc[mt][nt][r] = 0.0f;

    const int am[2] = { (tid + 0) >> 2, (tid + 256) >> 2 };
    const int aq[2] = { (tid + 0) & 3,  (tid + 256) & 3 };
    const int bkp   = tid >> 5;
    const int bn0   = (tid & 31) * 4;

    float4 pa[2], pb0, pb1;

    auto prefetch = [&](int k0) {
#pragma unroll
        for (int it = 0; it < 2; it++)
            pa[it] = *(const float4*)(A + (size_t)(brow + am[it]) * K + k0 + aq[it] * 4);
        pb0 = *(const float4*)(B + (size_t)(k0 + 2 * bkp) * N + bcol + bn0);
        pb1 = *(const float4*)(B + (size_t)(k0 + 2 * bkp + 1) * N + bcol + bn0);
    };
    auto stage = [&](int buf) {
#pragma unroll
        for (int it = 0; it < 2; it++) {
            uint32_t h0, l0, h1, l1;
            split2(pa[it].x, pa[it].y, h0, l0);
            split2(pa[it].z, pa[it].w, h1, l1);
            int base = am[it] * GASTR + aq[it] * 2;
            Ah[buf][base] = h0;  Ah[buf][base + 1] = h1;
            Al[buf][base] = l0;  Al[buf][base + 1] = l1;
        }
        uint32_t h[4], l[4];
        split2(pb0.x, pb1.x, h[0], l[0]);
        split2(pb0.y, pb1.y, h[1], l[1]);
        split2(pb0.z, pb1.z, h[2], l[2]);
        split2(pb0.w, pb1.w, h[3], l[3]);
        *(uint4*)&Bh[buf][bkp * GBSTR + bn0] = make_uint4(h[0], h[1], h[2], h[3]);
        *(uint4*)&Bl[buf][bkp * GBSTR + bn0] = make_uint4(l[0], l[1], l[2], l[3]);
    };

    prefetch(0);
    stage(0);
    __syncthreads();

    int buf = 0;
    for (int k0 = 0; k0 < K; k0 += 16) {
        const bool has_next = (k0 + 16) < K;
        if (has_next) prefetch(k0 + 16);

        uint32_t bh[4][2], bl[4][2];
#pragma unroll
        for (int nt = 0; nt < 4; nt++) {
            const int col = wn + nt * 8 + g;
            bh[nt][0] = Bh[buf][t * GBSTR + col];
            bh[nt][1] = Bh[buf][(t + 4) * GBSTR + col];
            bl[nt][0] = Bl[buf][t * GBSTR + col];
            bl[nt][1] = Bl[buf][(t + 4) * GBSTR + col];
        }
#pragma unroll
        for (int mt = 0; mt < 4; mt++) {
            const int r = wm + mt * 16 + g;
            uint32_t ah0 = Ah[buf][r * GASTR + t];
            uint32_t ah1 = Ah[buf][(r + 8) * GASTR + t];
            uint32_t ah2 = Ah[buf][r * GASTR + t + 4];
            uint32_t ah3 = Ah[buf][(r + 8) * GASTR + t + 4];
            uint32_t al0 = Al[buf][r * GASTR + t];
            uint32_t al1 = Al[buf][(r + 8) * GASTR + t];
            uint32_t al2 = Al[buf][r * GASTR + t + 4];
            uint32_t al3 = Al[buf][(r + 8) * GASTR + t + 4];
#pragma unroll
            for (int nt = 0; nt < 4; nt++) {
                mma_bf16(acc[mt][nt], ah0, ah1, ah2, ah3, bh[nt][0], bh[nt][1]);
                mma_bf16(acc[mt][nt], ah0, ah1, ah2, ah3, bl[nt][0], bl[nt][1]);
                mma_bf16(acc[mt][nt], al0, al1, al2, al3, bh[nt][0], bh[nt][1]);
            }
        }

        if (has_next) {
            stage(buf ^ 1);
            __syncthreads();
            buf ^= 1;
        }
    }

#pragma unroll
    for (int nt = 0; nt < 4; nt++) {
        const int col = bcol + wn + nt * 8 + 2 * t;
        const float2 bv = *(const float2*)(bias + col);
#pragma unroll
        for (int mt = 0; mt < 4; mt++) {
            const int row0 = brow + wm + mt * 16 + g;
            float v00 = acc[mt][nt][0] + bv.x, v01 = acc[mt][nt][1] + bv.y;
            float v10 = acc[mt][nt][2] + bv.x, v11 = acc[mt][nt][3] + bv.y;
            if (mode == 0) {
                *(float2*)(Cf + (size_t)row0 * N + col)       = make_float2(v00, v01);
                *(float2*)(Cf + (size_t)(row0 + 8) * N + col) = make_float2(v10, v11);
            } else {
                uint32_t h, l;
                size_t i0 = ((size_t)row0 * N + col) >> 1;
                split2(v00, v01, h, l);  Chi[i0] = h;  Clo[i0] = l;
                size_t i1 = ((size_t)(row0 + 8) * N + col) >> 1;
                split2(v10, v11, h, l);  Chi[i1] = h;  Clo[i1] = l;
            }
        }
    }
}

// ---------------------------------------------------------------------------
// Flash attention v2: Q fragments via smem+ldmatrix (register diet -> 2 CTA/SM)
// Dynamic smem (u32): Qh[128*36] Ql[128*36] Ksh[64*36] Ksl[64*36]
//                     Vsh[32*72] Vsl[32*72]  = 18432 u32 = 73728 B
// ---------------------------------------------------------------------------
#define QSTR 36
#define KSTR 36
#define VSTR 72
#define OFF_QL (128 * QSTR)
#define OFF_KH (2 * 128 * QSTR)
#define OFF_KL (OFF_KH + 64 * KSTR)
#define OFF_VH (OFF_KL + 64 * KSTR)
#define OFF_VL (OFF_VH + 32 * VSTR)
#define FL_SMEM ((OFF_VL + 32 * VSTR) * 4)   // 73728 bytes

__global__ __launch_bounds__(256, 2)
void flash_bf16x3(const uint32_t* __restrict__ qh,
                  const uint32_t* __restrict__ ql,
                  float* __restrict__ out)
{
    extern __shared__ uint32_t sm[];
    uint32_t* Qh  = sm;
    uint32_t* Ql  = sm + OFF_QL;
    uint32_t* Ksh = sm + OFF_KH;
    uint32_t* Ksl = sm + OFF_KL;
    uint32_t* Vsh = sm + OFF_VH;
    uint32_t* Vsl = sm + OFF_VL;
    const uint32_t sb = (uint32_t)__cvta_generic_to_shared(sm);

    const int qbx = gridDim.x - 1 - blockIdx.x;   // big tiles first
    const int h   = blockIdx.y;
    const int b   = blockIdx.z;

    const int tid  = threadIdx.x;
    const int wid  = tid >> 5;
    const int lane = tid & 31;
    const int g = lane >> 2;
    const int t = lane & 3;

    const int qoff = h * 32;
    const int koff = 512 + h * 32;
    const int voff = 1024 + h * 32;

    const int wq = qbx * 128 + wid * 16;

    // --- stage Q (hi+lo) to smem once ---
#pragma unroll
    for (int it = 0; it < 16; it++) {
        int idx = tid + it * 256;            // 0..4095
        int row = idx >> 5;
        int dp  = idx & 31;
        size_t gi = (size_t)(b * SEQ + qbx * 128 + row) * LD32 + qoff + dp;
        Qh[row * QSTR + dp] = qh[gi];
        Ql[row * QSTR + dp] = ql[gi];
    }

    // per-warp ldmatrix addressing for Q A-fragments
    const uint32_t qrow = (uint32_t)(wid * 16 + (lane & 15));
    const uint32_t qka  = (uint32_t)((lane >> 4) * 16);
    const uint32_t qaH  = sb + qrow * (QSTR * 4) + qka;
    const uint32_t qaL  = qaH + OFF_QL * 4;

    float oa[8][4];
#pragma unroll
    for (int nt = 0; nt < 8; nt++)
#pragma unroll
        for (int r = 0; r < 4; r++) oa[nt][r] = 0.0f;
    float m0 = -1e30f, m1 = -1e30f, l0 = 0.0f, l1 = 0.0f;

    const int r0g = wq + g;
    const int r1g = wq + g + 8;
    const int nblocks = 2 * qbx + 2;

    for (int jb = 0; jb < nblocks; jb++) {
        __syncthreads();   // also covers initial Q staging
#pragma unroll
        for (int i = 0; i < 8; i++) {
            int idx = tid + i * 256;
            int tok = idx >> 5, dp = idx & 31;
            size_t gi = (size_t)(b * SEQ + jb * 64 + tok) * LD32 + koff + dp;
            Ksh[tok * KSTR + dp] = qh[gi];
            Ksl[tok * KSTR + dp] = ql[gi];
        }
#pragma unroll
        for (int i = 0; i < 4; i++) {
            int idx = tid + i * 256;
            int r = idx >> 5, j = idx & 31;
            size_t g0 = (size_t)(b * SEQ + jb * 64 + 2 * r) * LD32 + voff + j;
            uint32_t a0 = qh[g0], b0 = qh[g0 + LD32];
            Vsh[r * VSTR + 2 * j]     = __byte_perm(a0, b0, 0x5410);
            Vsh[r * VSTR + 2 * j + 1] = __byte_perm(a0, b0, 0x7632);
            uint32_t a1 = ql[g0], b1 = ql[g0 + LD32];
            Vsl[r * VSTR + 2 * j]     = __byte_perm(a1, b1, 0x5410);
            Vsl[r * VSTR + 2 * j + 1] = __byte_perm(a1, b1, 0x7632);
        }
        __syncthreads();

        if (jb * 64 > wq + 15) continue;

        float sc[8][4];
#pragma unroll
        for (int nt = 0; nt < 8; nt++)
#pragma unroll
            for (int r = 0; r < 4; r++) sc[nt][r] = 0.0f;

#pragma unroll
        for (int s = 0; s < 4; s++) {
            uint32_t qh0, qh1, qh2, qh3, ql0, ql1, ql2, ql3;
            ldsm4(qh0, qh1, qh2, qh3, qaH + (uint32_t)(s * 32));
            ldsm4(ql0, ql1, ql2, ql3, qaL + (uint32_t)(s * 32));
#pragma unroll
            for (int nt = 0; nt < 8; nt++) {
                const int tok = nt * 8 + g;
                uint32_t kh0 = Ksh[tok * KSTR + s * 8 + t];
                uint32_t kh1 = Ksh[tok * KSTR + s * 8 + t + 4];
                uint32_t kl0 = Ksl[tok * KSTR + s * 8 + t];
                uint32_t kl1 = Ksl[tok * KSTR + s * 8 + t + 4];
                mma_bf16(sc[nt], qh0, qh1, qh2, qh3, kh0, kh1);
                mma_bf16(sc[nt], qh0, qh1, qh2, qh3, kl0, kl1);
                mma_bf16(sc[nt], ql0, ql1, ql2, ql3, kh0, kh1);
            }
        }

        if (jb * 64 + 63 > wq) {
#pragma unroll
            for (int nt = 0; nt < 8; nt++) {
                int c = jb * 64 + nt * 8 + 2 * t;
                if (c > r0g)     sc[nt][0] = -1e30f;
                if (c + 1 > r0g) sc[nt][1] = -1e30f;
                if (c > r1g)     sc[nt][2] = -1e30f;
                if (c + 1 > r1g) sc[nt][3] = -1e30f;
            }
        }

        float mx0 = -1e30f, mx1 = -1e30f;
#pragma unroll
        for (int nt = 0; nt < 8; nt++) {
            mx0 = fmaxf(mx0, fmaxf(sc[nt][0], sc[nt][1]));
            mx1 = fmaxf(mx1, fmaxf(sc[nt][2], sc[nt][3]));
        }
#pragma unroll
        for (int off = 1; off <= 2; off <<= 1) {
            mx0 = fmaxf(mx0, __shfl_xor_sync(0xffffffffu, mx0, off));
            mx1 = fmaxf(mx1, __shfl_xor_sync(0xffffffffu, mx1, off));
        }
        float mn0 = fmaxf(m0, mx0), mn1 = fmaxf(m1, mx1);
        float corr0 = __expf(m0 - mn0), corr1 = __expf(m1 - mn1);
        float s0 = 0.0f, s1 = 0.0f;
#pragma unroll
        for (int nt = 0; nt < 8; nt++) {
            sc[nt][0] = __expf(sc[nt][0] - mn0);
            sc[nt][1] = __expf(sc[nt][1] - mn0);
            sc[nt][2] = __expf(sc[nt][2] - mn1);
            sc[nt][3] = __expf(sc[nt][3] - mn1);
            s0 += sc[nt][0] + sc[nt][1];
            s1 += sc[nt][2] + sc[nt][3];
        }
#pragma unroll
        for (int off = 1; off <= 2; off <<= 1) {
            s0 += __shfl_xor_sync(0xffffffffu, s0, off);
            s1 += __shfl_xor_sync(0xffffffffu, s1, off);
        }
        l0 = l0 * corr0 + s0;  m0 = mn0;
        l1 = l1 * corr1 + s1;  m1 = mn1;
#pragma unroll
        for (int nt = 0; nt < 8; nt++) {
            oa[nt][0] *= corr0;  oa[nt][1] *= corr0;
            oa[nt][2] *= corr1;  oa[nt][3] *= corr1;
        }

#pragma unroll
        for (int s = 0; s < 4; s++) {
            uint32_t ph[4], pl[4];
            split2(sc[2 * s][0],     sc[2 * s][1],     ph[0], pl[0]);
            split2(sc[2 * s][2],     sc[2 * s][3],     ph[1], pl[1]);
            split2(sc[2 * s + 1][0], sc[2 * s + 1][1], ph[2], pl[2]);
            split2(sc[2 * s + 1][2], sc[2 * s + 1][3], ph[3], pl[3]);
#pragma unroll
            for (int nt = 0; nt < 8; nt++) {
                const int d = nt * 8 + g;
                uint32_t vh0 = Vsh[(s * 8 + t) * VSTR + d];
                uint32_t vh1 = Vsh[(s * 8 + t + 4) * VSTR + d];
                uint32_t vl0 = Vsl[(s * 8 + t) * VSTR + d];
                uint32_t vl1 = Vsl[(s * 8 + t + 4) * VSTR + d];
                mma_bf16(oa[nt], ph[0], ph[1], ph[2], ph[3], vh0, vh1);
                mma_bf16(oa[nt], ph[0], ph[1], ph[2], ph[3], vl0, vl1);
                mma_bf16(oa[nt], pl[0], pl[1], pl[2], pl[3], vh0, vh1);
            }
        }
    }

    const float inv0 = 1.0f / l0, inv1 = 1.0f / l1;
    const size_t orow0 = (size_t)(b * SEQ + r0g) * HIDDEN + h * HDIM;
    const size_t orow1 = (size_t)(b * SEQ + r1g) * HIDDEN + h * HDIM;
#pragma unroll
    for (int nt = 0; nt < 8; nt++) {
        const int d = nt * 8 + 2 * t;
        *(float2*)(out + orow0 + d) = make_float2(oa[nt][0] * inv0, oa[nt][1] * inv0);
        *(float2*)(out + orow1 + d) = make_float2(oa[nt][2] * inv1, oa[nt][3] * inv1);
    }
}

// ---------------------------------------------------------------------------
// Launch
// ---------------------------------------------------------------------------
extern "C" void kernel_launch(void* const* d_in, const int* in_sizes, int n_in,
                              void* d_out, int out_size)
{
    const float* hidden = (const float*)d_in[0];
    const float* w_attn = (const float*)d_in[1];
    const float* b_attn = (const float*)d_in[2];
    const float* w_proj = (const float*)d_in[3];
    const float* b_proj = (const float*)d_in[4];
    float* out = (float*)d_out;

    uint32_t *qh, *ql;
    float* attn;
    cudaGetSymbolAddress((void**)&qh, g_qh);
    cudaGetSymbolAddress((void**)&ql, g_ql);
    cudaGetSymbolAddress((void**)&attn, g_attn);

    static bool attr_set = false;
    if (!attr_set) {
        cudaFuncSetAttribute(flash_bf16x3,
                             cudaFuncAttributeMaxDynamicSharedMemorySize, FL_SMEM);
        attr_set = true;
    }

    // 1) QKV projection -> split bf16 planes (R3 kernel, at HMMA cap)
    {
        dim3 grid(QKV_N / 128, M_TOK / 128);
        gemm_bf16x3<<<grid, 256>>>(hidden, w_attn, b_attn,
                                   nullptr, qh, ql,
                                   M_TOK, QKV_N, HIDDEN, 1);
    }
    // 2) flash attention (2 CTA/SM) -> fp32 attn
    {
        dim3 grid(SEQ / 128, NHEAD, BATCH);
        flash_bf16x3<<<grid, 256, FL_SMEM>>>(qh, ql, attn);
    }
    // 3) output projection -> fp32 out (bf16x3, reverted from int8)
    {
        dim3 grid(HIDDEN / 128, M_TOK / 128);
        gemm_bf16x3<<<grid, 256>>>(attn, w_proj, b_proj,
                                   out, nullptr, nullptr,
                                   M_TOK, HIDDEN, HIDDEN, 0);
    }
}

// round 9
// speedup vs baseline: 1.1639x; 1.0200x over previous
#include <cuda_runtime.h>
#include <cuda_bf16.h>
#include <math.h>
#include <stdint.h>

// ---------------------------------------------------------------------------
// Problem constants
// ---------------------------------------------------------------------------
#define BATCH 2
#define SEQ 2048
#define HIDDEN 1024
#define NHEAD 16
#define HDIM 64
#define M_TOK (BATCH * SEQ)          // 4096
#define QKV_N (3 * HIDDEN)           // 3072
#define LD32 (QKV_N / 2)             // 1536 u32 per token row (qkv planes)

// Scratch (__device__ globals per allocation rules)
__device__ uint32_t g_qh[(size_t)M_TOK * LD32];      // qkv hi plane
__device__ uint32_t g_ql[(size_t)M_TOK * LD32];      // qkv lo plane
__device__ float    g_attn[(size_t)M_TOK * HIDDEN];  // attention output fp32

// ---------------------------------------------------------------------------
// Helpers
// ---------------------------------------------------------------------------
__device__ __forceinline__ void split2(float x, float y,
                                       uint32_t& hi, uint32_t& lo) {
    __nv_bfloat162 h = __floats2bfloat162_rn(x, y);
    float2 hf = __bfloat1622float2(h);
    __nv_bfloat162 l = __floats2bfloat162_rn(x - hf.x, y - hf.y);
    hi = *reinterpret_cast<uint32_t*>(&h);
    lo = *reinterpret_cast<uint32_t*>(&l);
}

__device__ __forceinline__ void mma_bf16(float* c, uint32_t a0, uint32_t a1,
                                         uint32_t a2, uint32_t a3,
                                         uint32_t b0, uint32_t b1) {
    asm volatile(
        "mma.sync.aligned.m16n8k16.row.col.f32.bf16.bf16.f32 "
        "{%0,%1,%2,%3}, {%4,%5,%6,%7}, {%8,%9}, {%0,%1,%2,%3};"
        : "+f"(c[0]), "+f"(c[1]), "+f"(c[2]), "+f"(c[3])
        : "r"(a0), "r"(a1), "r"(a2), "r"(a3), "r"(b0), "r"(b1));
}

__device__ __forceinline__ void ldsm4(uint32_t& r0, uint32_t& r1,
                                      uint32_t& r2, uint32_t& r3, uint32_t a) {
    asm volatile("ldmatrix.sync.aligned.m8n8.x4.shared.b16 {%0,%1,%2,%3}, [%4];"
                 : "=r"(r0), "=r"(r1), "=r"(r2), "=r"(r3) : "r"(a));
}

__device__ __forceinline__ void ldsm4t(uint32_t& r0, uint32_t& r1,
                                       uint32_t& r2, uint32_t& r3, uint32_t a) {
    asm volatile("ldmatrix.sync.aligned.m8n8.x4.trans.shared.b16 {%0,%1,%2,%3}, [%4];"
                 : "=r"(r0), "=r"(r1), "=r"(r2), "=r"(r3) : "r"(a));
}

__device__ __forceinline__ void cp16(uint32_t smem, const void* gmem) {
    asm volatile("cp.async.ca.shared.global [%0], [%1], 16;"
                 :: "r"(smem), "l"(gmem));
}
#define CP_COMMIT() asm volatile("cp.async.commit_group;" ::: "memory")
#define CP_WAIT(n)  asm volatile("cp.async.wait_group %0;" :: "n"(n) : "memory")

// ---------------------------------------------------------------------------
// bf16x3 GEMM + bias (R3 kernel, at the HMMA cap): C = A[M,K] @ B[K,N] + bias
// mode 0: fp32 C. mode 1: split bf16 planes Chi/Clo.
// ---------------------------------------------------------------------------
#define GASTR 12
#define GBSTR 136

__global__ __launch_bounds__(256)
void gemm_bf16x3(const float* __restrict__ A, const float* __restrict__ B,
                 const float* __restrict__ bias,
                 float* __restrict__ Cf,
                 uint32_t* __restrict__ Chi, uint32_t* __restrict__ Clo,
                 int M, int N, int K, int mode)
{
    __shared__ uint32_t Ah[2][128 * GASTR], Al[2][128 * GASTR];
    __shared__ uint32_t Bh[2][8 * GBSTR],  Bl[2][8 * GBSTR];

    const int tid  = threadIdx.x;
    const int warp = tid >> 5;
    const int lane = tid & 31;
    const int g = lane >> 2;
    const int t = lane & 3;
    const int wm = (warp >> 2) * 64;
    const int wn = (warp & 3) * 32;
    const int brow = blockIdx.y * 128;
    const int bcol = blockIdx.x * 128;

    float acc[4][4][4];
#pragma unroll
    for (int mt = 0; mt < 4; mt++)
#pragma unroll
        for (int nt = 0; nt < 4; nt++)
#pragma unroll
            for (int r = 0; r < 4; r++) acc[mt][nt][r] = 0.0f;

    const int am[2] = { (tid + 0) >> 2, (tid + 256) >> 2 };
    const int aq[2] = { (tid + 0) & 3,  (tid + 256) & 3 };
    const int bkp   = tid >> 5;
    const int bn0   = (tid & 31) * 4;

    float4 pa[2], pb0, pb1;

    auto prefetch = [&](int k0) {
#pragma unroll
        for (int it = 0; it < 2; it++)
            pa[it] = *(const float4*)(A + (size_t)(brow + am[it]) * K + k0 + aq[it] * 4);
        pb0 = *(const float4*)(B + (size_t)(k0 + 2 * bkp) * N + bcol + bn0);
        pb1 = *(const float4*)(B + (size_t)(k0 + 2 * bkp + 1) * N + bcol + bn0);
    };
    auto stage = [&](int buf) {
#pragma unroll
        for (int it = 0; it < 2; it++) {
            uint32_t h0, l0, h1, l1;
            split2(pa[it].x, pa[it].y, h0, l0);
            split2(pa[it].z, pa[it].w, h1, l1);
            int base = am[it] * GASTR + aq[it] * 2;
            Ah[buf][base] = h0;  Ah[buf][base + 1] = h1;
            Al[buf][base] = l0;  Al[buf][base + 1] = l1;
        }
        uint32_t h[4], l[4];
        split2(pb0.x, pb1.x, h[0], l[0]);
        split2(pb0.y, pb1.y, h[1], l[1]);
        split2(pb0.z, pb1.z, h[2], l[2]);
        split2(pb0.w, pb1.w, h[3], l[3]);
        *(uint4*)&Bh[buf][bkp * GBSTR + bn0] = make_uint4(h[0], h[1], h[2], h[3]);
        *(uint4*)&Bl[buf][bkp * GBSTR + bn0] = make_uint4(l[0], l[1], l[2], l[3]);
    };

    prefetch(0);
    stage(0);
    __syncthreads();

    int buf = 0;
    for (int k0 = 0; k0 < K; k0 += 16) {
        const bool has_next = (k0 + 16) < K;
        if (has_next) prefetch(k0 + 16);

        uint32_t bh[4][2], bl[4][2];
#pragma unroll
        for (int nt = 0; nt < 4; nt++) {
            const int col = wn + nt * 8 + g;
            bh[nt][0] = Bh[buf][t * GBSTR + col];
            bh[nt][1] = Bh[buf][(t + 4) * GBSTR + col];
            bl[nt][0] = Bl[buf][t * GBSTR + col];
            bl[nt][1] = Bl[buf][(t + 4) * GBSTR + col];
        }
#pragma unroll
        for (int mt = 0; mt < 4; mt++) {
            const int r = wm + mt * 16 + g;
            uint32_t ah0 = Ah[buf][r * GASTR + t];
            uint32_t ah1 = Ah[buf][(r + 8) * GASTR + t];
            uint32_t ah2 = Ah[buf][r * GASTR + t + 4];
            uint32_t ah3 = Ah[buf][(r + 8) * GASTR + t + 4];
            uint32_t al0 = Al[buf][r * GASTR + t];
            uint32_t al1 = Al[buf][(r + 8) * GASTR + t];
            uint32_t al2 = Al[buf][r * GASTR + t + 4];
            uint32_t al3 = Al[buf][(r + 8) * GASTR + t + 4];
#pragma unroll
            for (int nt = 0; nt < 4; nt++) {
                mma_bf16(acc[mt][nt], ah0, ah1, ah2, ah3, bh[nt][0], bh[nt][1]);
                mma_bf16(acc[mt][nt], ah0, ah1, ah2, ah3, bl[nt][0], bl[nt][1]);
                mma_bf16(acc[mt][nt], al0, al1, al2, al3, bh[nt][0], bh[nt][1]);
            }
        }

        if (has_next) {
            stage(buf ^ 1);
            __syncthreads();
            buf ^= 1;
        }
    }

#pragma unroll
    for (int nt = 0; nt < 4; nt++) {
        const int col = bcol + wn + nt * 8 + 2 * t;
        const float2 bv = *(const float2*)(bias + col);
#pragma unroll
        for (int mt = 0; mt < 4; mt++) {
            const int row0 = brow + wm + mt * 16 + g;
            float v00 = acc[mt][nt][0] + bv.x, v01 = acc[mt][nt][1] + bv.y;
            float v10 = acc[mt][nt][2] + bv.x, v11 = acc[mt][nt][3] + bv.y;
            if (mode == 0) {
                *(float2*)(Cf + (size_t)row0 * N + col)       = make_float2(v00, v01);
                *(float2*)(Cf + (size_t)(row0 + 8) * N + col) = make_float2(v10, v11);
            } else {
                uint32_t h, l;
                size_t i0 = ((size_t)row0 * N + col) >> 1;
                split2(v00, v01, h, l);  Chi[i0] = h;  Clo[i0] = l;
                size_t i1 = ((size_t)(row0 + 8) * N + col) >> 1;
                split2(v10, v11, h, l);  Chi[i1] = h;  Clo[i1] = l;
            }
        }
    }
}

// ---------------------------------------------------------------------------
// Flash attention v3: cp.async double-buffered K/V (natural layout) +
// ldmatrix (non-trans for K, trans for V) fragments. 2 CTAs/SM.
// smem u32 layout: Qh[128*36] Ql[128*36] | buf0: KH KL VH VL (each 64*36)
//                  | buf1: same.  Total 27648 u32 = 110592 B.
// Row stride 144B -> ldmatrix rows hit distinct 16B regions (9r mod 8 = r).
// ---------------------------------------------------------------------------
#define FSTR 36
#define OFF_QL (128 * FSTR)               // 4608
#define OFF_BUF (2 * 128 * FSTR)          // 9216
#define BUF_SZ  (4 * 64 * FSTR)           // 9216 (KH KL VH VL)
#define PL_SZ   (64 * FSTR)               // 2304
#define FL_SMEM ((OFF_BUF + 2 * BUF_SZ) * 4)   // 110592 bytes

__global__ __launch_bounds__(256, 2)
void flash_bf16x3(const uint32_t* __restrict__ qh,
                  const uint32_t* __restrict__ ql,
                  float* __restrict__ out)
{
    extern __shared__ uint32_t sm[];
    uint32_t* Qh = sm;
    uint32_t* Ql = sm + OFF_QL;
    const uint32_t sb = (uint32_t)__cvta_generic_to_shared(sm);

    const int qbx = gridDim.x - 1 - blockIdx.x;   // big tiles first
    const int h   = blockIdx.y;
    const int b   = blockIdx.z;

    const int tid  = threadIdx.x;
    const int wid  = tid >> 5;
    const int lane = tid & 31;
    const int g = lane >> 2;
    const int t = lane & 3;

    const int qoff = h * 32;
    const int koff = 512 + h * 32;
    const int voff = 1024 + h * 32;

    const int wq = qbx * 128 + wid * 16;

    // --- stage Q (hi+lo) to smem once ---
#pragma unroll
    for (int it = 0; it < 16; it++) {
        int idx = tid + it * 256;            // 0..4095
        int row = idx >> 5;
        int dp  = idx & 31;
        size_t gi = (size_t)(b * SEQ + qbx * 128 + row) * LD32 + qoff + dp;
        Qh[row * FSTR + dp] = qh[gi];
        Ql[row * FSTR + dp] = ql[gi];
    }

    // cp.async task mapping: 512 tasks/plane, 2 per thread
    const int crow = tid >> 3;               // row pair-base: tasks tid, tid+256
    const int cch  = tid & 7;
    auto issue_blk = [&](int jb, int buf) {
        const uint32_t base = sb + (uint32_t)((OFF_BUF + buf * BUF_SZ) * 4);
        const size_t trow = (size_t)(b * SEQ + jb * 64);
#pragma unroll
        for (int i = 0; i < 2; i++) {
            int row = crow + i * 32;
            uint32_t so = (uint32_t)(row * 144 + cch * 16);
            size_t gr = (trow + row) * LD32 + cch * 4;
            cp16(base + 0 * (PL_SZ * 4) + so, qh + gr + koff);
            cp16(base + 1 * (PL_SZ * 4) + so, ql + gr + koff);
            cp16(base + 2 * (PL_SZ * 4) + so, qh + gr + voff);
            cp16(base + 3 * (PL_SZ * 4) + so, ql + gr + voff);
        }
        CP_COMMIT();
    };

    // fragment addressing
    const uint32_t qa   = sb + (uint32_t)((wid * 16 + (lane & 15)) * 144 +
                                          (lane >> 4) * 16);
    const uint32_t krow = (uint32_t)((lane & 7) + ((lane >> 4) & 1) * 8);
    const uint32_t kcol = (uint32_t)(((lane >> 3) & 1) * 16);
    const uint32_t vrow = (uint32_t)(lane & 15);
    const uint32_t vcol = (uint32_t)(((lane >> 4) & 1) * 16);

    float oa[8][4];
#pragma unroll
    for (int nt = 0; nt < 8; nt++)
#pragma unroll
        for (int r = 0; r < 4; r++) oa[nt][r] = 0.0f;
    float m0 = -1e30f, m1 = -1e30f, l0 = 0.0f, l1 = 0.0f;

    const int r0g = wq + g;
    const int r1g = wq + g + 8;
    const int nblocks = 2 * qbx + 2;

    issue_blk(0, 0);
    issue_blk(1, 1);

    for (int jb = 0; jb < nblocks; jb++) {
        if (jb + 1 < nblocks) CP_WAIT(1); else CP_WAIT(0);
        __syncthreads();   // data visible; also covers Q staging on jb=0

        if (jb * 64 <= wq + 15) {
            const uint32_t kbH = sb + (uint32_t)((OFF_BUF + (jb & 1) * BUF_SZ) * 4);
            const uint32_t kbL = kbH + PL_SZ * 4;
            const uint32_t vbH = kbL + PL_SZ * 4;
            const uint32_t vbL = vbH + PL_SZ * 4;

            float sc[8][4];
#pragma unroll
            for (int nt = 0; nt < 8; nt++)
#pragma unroll
                for (int r = 0; r < 4; r++) sc[nt][r] = 0.0f;

            // --- S = Q K^T ---
#pragma unroll
            for (int s = 0; s < 4; s++) {
                uint32_t q0, q1, q2, q3, p0, p1, p2, p3;
                ldsm4(q0, q1, q2, q3, qa + (uint32_t)(s * 32));
                ldsm4(p0, p1, p2, p3, qa + (uint32_t)(OFF_QL * 4 + s * 32));
#pragma unroll
                for (int np = 0; np < 4; np++) {
                    const uint32_t ro = (uint32_t)((np * 16 + krow) * 144) +
                                        (uint32_t)(s * 32) + kcol;
                    uint32_t kh0, kh1, kh2, kh3, kl0, kl1, kl2, kl3;
                    ldsm4(kh0, kh1, kh2, kh3, kbH + ro);
                    ldsm4(kl0, kl1, kl2, kl3, kbL + ro);
                    mma_bf16(sc[2 * np],     q0, q1, q2, q3, kh0, kh1);
                    mma_bf16(sc[2 * np],     q0, q1, q2, q3, kl0, kl1);
                    mma_bf16(sc[2 * np],     p0, p1, p2, p3, kh0, kh1);
                    mma_bf16(sc[2 * np + 1], q0, q1, q2, q3, kh2, kh3);
                    mma_bf16(sc[2 * np + 1], q0, q1, q2, q3, kl2, kl3);
                    mma_bf16(sc[2 * np + 1], p0, p1, p2, p3, kh2, kh3);
                }
            }

            // --- causal mask (diagonal-crossing blocks) ---
            if (jb * 64 + 63 > wq) {
#pragma unroll
                for (int nt = 0; nt < 8; nt++) {
                    int c = jb * 64 + nt * 8 + 2 * t;
                    if (c > r0g)     sc[nt][0] = -1e30f;
                    if (c + 1 > r0g) sc[nt][1] = -1e30f;
                    if (c > r1g)     sc[nt][2] = -1e30f;
                    if (c + 1 > r1g) sc[nt][3] = -1e30f;
                }
            }

            // --- online softmax ---
            float mx0 = -1e30f, mx1 = -1e30f;
#pragma unroll
            for (int nt = 0; nt < 8; nt++) {
                mx0 = fmaxf(mx0, fmaxf(sc[nt][0], sc[nt][1]));
                mx1 = fmaxf(mx1, fmaxf(sc[nt][2], sc[nt][3]));
            }
#pragma unroll
            for (int off = 1; off <= 2; off <<= 1) {
                mx0 = fmaxf(mx0, __shfl_xor_sync(0xffffffffu, mx0, off));
                mx1 = fmaxf(mx1, __shfl_xor_sync(0xffffffffu, mx1, off));
            }
            float mn0 = fmaxf(m0, mx0), mn1 = fmaxf(m1, mx1);
            float corr0 = __expf(m0 - mn0), corr1 = __expf(m1 - mn1);
            float s0 = 0.0f, s1 = 0.0f;
#pragma unroll
            for (int nt = 0; nt < 8; nt++) {
                sc[nt][0] = __expf(sc[nt][0] - mn0);
                sc[nt][1] = __expf(sc[nt][1] - mn0);
                sc[nt][2] = __expf(sc[nt][2] - mn1);
                sc[nt][3] = __expf(sc[nt][3] - mn1);
                s0 += sc[nt][0] + sc[nt][1];
                s1 += sc[nt][2] + sc[nt][3];
            }
#pragma unroll
            for (int off = 1; off <= 2; off <<= 1) {
                s0 += __shfl_xor_sync(0xffffffffu, s0, off);
                s1 += __shfl_xor_sync(0xffffffffu, s1, off);
            }
            l0 = l0 * corr0 + s0;  m0 = mn0;
            l1 = l1 * corr1 + s1;  m1 = mn1;
#pragma unroll
            for (int nt = 0; nt < 8; nt++) {
                oa[nt][0] *= corr0;  oa[nt][1] *= corr0;
                oa[nt][2] *= corr1;  oa[nt][3] *= corr1;
            }

            // --- O += P V  (V B-frags via ldmatrix.trans on natural layout) ---
#pragma unroll
            for (int s = 0; s < 4; s++) {
                uint32_t ph[4], pl[4];
                split2(sc[2 * s][0],     sc[2 * s][1],     ph[0], pl[0]);
                split2(sc[2 * s][2],     sc[2 * s][3],     ph[1], pl[1]);
                split2(sc[2 * s + 1][0], sc[2 * s + 1][1], ph[2], pl[2]);
                split2(sc[2 * s + 1][2], sc[2 * s + 1][3], ph[3], pl[3]);
#pragma unroll
                for (int np = 0; np < 4; np++) {
                    const uint32_t ro = (uint32_t)((s * 16 + vrow) * 144) +
                                        (uint32_t)(np * 32) + vcol;
                    uint32_t vh0, vh1, vh2, vh3, vl0, vl1, vl2, vl3;
                    ldsm4t(vh0, vh1, vh2, vh3, vbH + ro);
                    ldsm4t(vl0, vl1, vl2, vl3, vbL + ro);
                    mma_bf16(oa[2 * np],     ph[0], ph[1], ph[2], ph[3], vh0, vh1);
                    mma_bf16(oa[2 * np],     ph[0], ph[1], ph[2], ph[3], vl0, vl1);
                    mma_bf16(oa[2 * np],     pl[0], pl[1], pl[2], pl[3], vh0, vh1);
                    mma_bf16(oa[2 * np + 1], ph[0], ph[1], ph[2], ph[3], vh2, vh3);
                    mma_bf16(oa[2 * np + 1], ph[0], ph[1], ph[2], ph[3], vl2, vl3);
                    mma_bf16(oa[2 * np + 1], pl[0], pl[1], pl[2], pl[3], vh2, vh3);
                }
            }
        }

        __syncthreads();   // all reads of buf[jb&1] done
        if (jb + 2 < nblocks) issue_blk(jb + 2, jb & 1);
    }

    const float inv0 = 1.0f / l0, inv1 = 1.0f / l1;
    const size_t orow0 = (size_t)(b * SEQ + r0g) * HIDDEN + h * HDIM;
    const size_t orow1 = (size_t)(b * SEQ + r1g) * HIDDEN + h * HDIM;
#pragma unroll
    for (int nt = 0; nt < 8; nt++) {
        const int d = nt * 8 + 2 * t;
        *(float2*)(out + orow0 + d) = make_float2(oa[nt][0] * inv0, oa[nt][1] * inv0);
        *(float2*)(out + orow1 + d) = make_float2(oa[nt][2] * inv1, oa[nt][3] * inv1);
    }
}

// ---------------------------------------------------------------------------
// Launch
// ---------------------------------------------------------------------------
extern "C" void kernel_launch(void* const* d_in, const int* in_sizes, int n_in,
                              void* d_out, int out_size)
{
    const float* hidden = (const float*)d_in[0];
    const float* w_attn = (const float*)d_in[1];
    const float* b_attn = (const float*)d_in[2];
    const float* w_proj = (const float*)d_in[3];
    const float* b_proj = (const float*)d_in[4];
    float* out = (float*)d_out;

    uint32_t *qh, *ql;
    float* attn;
    cudaGetSymbolAddress((void**)&qh, g_qh);
    cudaGetSymbolAddress((void**)&ql, g_ql);
    cudaGetSymbolAddress((void**)&attn, g_attn);

    static bool attr_set = false;
    if (!attr_set) {
        cudaFuncSetAttribute(flash_bf16x3,
                             cudaFuncAttributeMaxDynamicSharedMemorySize, FL_SMEM);
        attr_set = true;
    }

    // 1) QKV projection -> split bf16 planes (at HMMA cap)
    {
        dim3 grid(QKV_N / 128, M_TOK / 128);
        gemm_bf16x3<<<grid, 256>>>(hidden, w_attn, b_attn,
                                   nullptr, qh, ql,
                                   M_TOK, QKV_N, HIDDEN, 1);
    }
    // 2) flash attention v3 -> fp32 attn
    {
        dim3 grid(SEQ / 128, NHEAD, BATCH);
        flash_bf16x3<<<grid, 256, FL_SMEM>>>(qh, ql, attn);
    }
    // 3) output projection -> fp32 out
    {
        dim3 grid(HIDDEN / 128, M_TOK / 128);
        gemm_bf16x3<<<grid, 256>>>(attn, w_proj, b_proj,
                                   out, nullptr, nullptr,
                                   M_TOK, HIDDEN, HIDDEN, 0);
    }
}

// round 10
// speedup vs baseline: 1.1797x; 1.0135x over previous
#include <cuda_runtime.h>
#include <cuda_bf16.h>
#include <math.h>
#include <stdint.h>

// ---------------------------------------------------------------------------
// Problem constants
// ---------------------------------------------------------------------------
#define BATCH 2
#define SEQ 2048
#define HIDDEN 1024
#define NHEAD 16
#define HDIM 64
#define M_TOK (BATCH * SEQ)          // 4096
#define QKV_N (3 * HIDDEN)           // 3072
#define LD32 (QKV_N / 2)             // 1536 u32 per token row (qkv planes)

// Scratch (__device__ globals per allocation rules)
__device__ uint32_t g_qh[(size_t)M_TOK * LD32];      // qkv hi plane
__device__ uint32_t g_ql[(size_t)M_TOK * LD32];      // qkv lo plane
__device__ float    g_attn[(size_t)M_TOK * HIDDEN];  // attention output fp32
__device__ int8_t   g_a1[(size_t)M_TOK * HIDDEN];    // attn digit1
__device__ int8_t   g_a2[(size_t)M_TOK * HIDDEN];    // attn digit2
__device__ int8_t   g_w1[(size_t)HIDDEN * HIDDEN];   // w_proj^T digit1 [n][k]
__device__ int8_t   g_w2[(size_t)HIDDEN * HIDDEN];   // w_proj^T digit2
__device__ unsigned g_maxA;                          // max|attn| (float bits)
__device__ unsigned g_maxW;                          // max|w_proj|

// ---------------------------------------------------------------------------
// Helpers
// ---------------------------------------------------------------------------
__device__ __forceinline__ void split2(float x, float y,
                                       uint32_t& hi, uint32_t& lo) {
    __nv_bfloat162 h = __floats2bfloat162_rn(x, y);
    float2 hf = __bfloat1622float2(h);
    __nv_bfloat162 l = __floats2bfloat162_rn(x - hf.x, y - hf.y);
    hi = *reinterpret_cast<uint32_t*>(&h);
    lo = *reinterpret_cast<uint32_t*>(&l);
}

__device__ __forceinline__ void mma_bf16(float* c, uint32_t a0, uint32_t a1,
                                         uint32_t a2, uint32_t a3,
                                         uint32_t b0, uint32_t b1) {
    asm volatile(
        "mma.sync.aligned.m16n8k16.row.col.f32.bf16.bf16.f32 "
        "{%0,%1,%2,%3}, {%4,%5,%6,%7}, {%8,%9}, {%0,%1,%2,%3};"
        : "+f"(c[0]), "+f"(c[1]), "+f"(c[2]), "+f"(c[3])
        : "r"(a0), "r"(a1), "r"(a2), "r"(a3), "r"(b0), "r"(b1));
}

__device__ __forceinline__ void mma_s8(int* c, uint32_t a0, uint32_t a1,
                                       uint32_t a2, uint32_t a3,
                                       uint32_t b0, uint32_t b1) {
    asm volatile(
        "mma.sync.aligned.m16n8k32.row.col.s32.s8.s8.s32 "
        "{%0,%1,%2,%3}, {%4,%5,%6,%7}, {%8,%9}, {%0,%1,%2,%3};"
        : "+r"(c[0]), "+r"(c[1]), "+r"(c[2]), "+r"(c[3])
        : "r"(a0), "r"(a1), "r"(a2), "r"(a3), "r"(b0), "r"(b1));
}

__device__ __forceinline__ void ldsm4(uint32_t& r0, uint32_t& r1,
                                      uint32_t& r2, uint32_t& r3, uint32_t a) {
    asm volatile("ldmatrix.sync.aligned.m8n8.x4.shared.b16 {%0,%1,%2,%3}, [%4];"
                 : "=r"(r0), "=r"(r1), "=r"(r2), "=r"(r3) : "r"(a));
}

__device__ __forceinline__ void ldsm4t(uint32_t& r0, uint32_t& r1,
                                       uint32_t& r2, uint32_t& r3, uint32_t a) {
    asm volatile("ldmatrix.sync.aligned.m8n8.x4.trans.shared.b16 {%0,%1,%2,%3}, [%4];"
                 : "=r"(r0), "=r"(r1), "=r"(r2), "=r"(r3) : "r"(a));
}

__device__ __forceinline__ void cp16(uint32_t smem, const void* gmem) {
    asm volatile("cp.async.ca.shared.global [%0], [%1], 16;"
                 :: "r"(smem), "l"(gmem));
}
#define CP_COMMIT() asm volatile("cp.async.commit_group;" ::: "memory")
#define CP_WAIT(n)  asm volatile("cp.async.wait_group %0;" :: "n"(n) : "memory")

// quantize x (|x| <= max) to q1*256 + q2 with S = 32512/max
__device__ __forceinline__ void quant2(float x, float S, int8_t& d1, int8_t& d2) {
    int q = __float2int_rn(x * S);
    int q1 = (q + 128) >> 8;
    d1 = (int8_t)q1;
    d2 = (int8_t)(q - (q1 << 8));
}

// ---------------------------------------------------------------------------
// max-abs reduction (for w_proj)
// ---------------------------------------------------------------------------
__global__ __launch_bounds__(256)
void maxabs_kernel(const float* __restrict__ x, int n, unsigned* __restrict__ out)
{
    float m = 0.0f;
    for (int i = blockIdx.x * 256 + threadIdx.x; i < n; i += gridDim.x * 256)
        m = fmaxf(m, fabsf(x[i]));
#pragma unroll
    for (int off = 16; off >= 1; off >>= 1)
        m = fmaxf(m, __shfl_xor_sync(0xffffffffu, m, off));
    if ((threadIdx.x & 31) == 0)
        atomicMax(out, __float_as_uint(m));
}

// ---------------------------------------------------------------------------
// quantize attn fp32 -> digit planes (maxA produced by flash epilogue)
// ---------------------------------------------------------------------------
__global__ __launch_bounds__(256)
void quant_attn_kernel(const float* __restrict__ x,
                       int8_t* __restrict__ d1, int8_t* __restrict__ d2, int n)
{
    const float maxv = fmaxf(__uint_as_float(g_maxA), 1e-30f);
    const float S = 32512.0f / maxv;
    int i = blockIdx.x * 256 + threadIdx.x;
    if (i < n) quant2(x[i], S, d1[i], d2[i]);
}

// ---------------------------------------------------------------------------
// transpose + quantize  W[K][N] -> digit planes [N][K]
// ---------------------------------------------------------------------------
__global__ __launch_bounds__(256)
void transpose_quant_kernel(const float* __restrict__ W,
                            int8_t* __restrict__ d1, int8_t* __restrict__ d2,
                            int K, int N)
{
    __shared__ float s[64][33];
    const int tid = threadIdx.x;
    const int k0 = blockIdx.y * 64;
    const int n0 = blockIdx.x * 32;
    const float maxv = fmaxf(__uint_as_float(g_maxW), 1e-30f);
    const float S = 32512.0f / maxv;

#pragma unroll
    for (int i = 0; i < 8; i++) {
        int idx = tid + i * 256;
        int nl = idx & 31;
        int kl = idx >> 5;
        s[kl][nl] = W[(size_t)(k0 + kl) * N + n0 + nl];
    }
    __syncthreads();

#pragma unroll
    for (int i = 0; i < 8; i++) {
        int idx = tid + i * 256;
        int kl = idx & 63;
        int nl = idx >> 6;
        size_t o = (size_t)(n0 + nl) * K + k0 + kl;
        quant2(s[kl][nl], S, d1[o], d2[o]);
    }
}

// ---------------------------------------------------------------------------
// bf16x3 GEMM + bias (at the HMMA cap): C = A[M,K] @ B[K,N] + bias
// mode 0: fp32 C. mode 1: split bf16 planes Chi/Clo.
// ---------------------------------------------------------------------------
#define GASTR 12
#define GBSTR 136

__global__ __launch_bounds__(256)
void gemm_bf16x3(const float* __restrict__ A, const float* __restrict__ B,
                 const float* __restrict__ bias,
                 float* __restrict__ Cf,
                 uint32_t* __restrict__ Chi, uint32_t* __restrict__ Clo,
                 int M, int N, int K, int mode)
{
    __shared__ uint32_t Ah[2][128 * GASTR], Al[2][128 * GASTR];
    __shared__ uint32_t Bh[2][8 * GBSTR],  Bl[2][8 * GBSTR];

    const int tid  = threadIdx.x;
    const int warp = tid >> 5;
    const int lane = tid & 31;
    const int g = lane >> 2;
    const int t = lane & 3;
    const int wm = (warp >> 2) * 64;
    const int wn = (warp & 3) * 32;
    const int brow = blockIdx.y * 128;
    const int bcol = blockIdx.x * 128;

    float acc[4][4][4];
#pragma unroll
    for (int mt = 0; mt < 4; mt++)
#pragma unroll
        for (int nt = 0; nt < 4; nt++)
#pragma unroll
            for (int r = 0; r < 4; r++) acc[mt][nt][r] = 0.0f;

    const int am[2] = { (tid + 0) >> 2, (tid + 256) >> 2 };
    const int aq[2] = { (tid + 0) & 3,  (tid + 256) & 3 };
    const int bkp   = tid >> 5;
    const int bn0   = (tid & 31) * 4;

    float4 pa[2], pb0, pb1;

    auto prefetch = [&](int k0) {
#pragma unroll
        for (int it = 0; it < 2; it++)
            pa[it] = *(const float4*)(A + (size_t)(brow + am[it]) * K + k0 + aq[it] * 4);
        pb0 = *(const float4*)(B + (size_t)(k0 + 2 * bkp) * N + bcol + bn0);
        pb1 = *(const float4*)(B + (size_t)(k0 + 2 * bkp + 1) * N + bcol + bn0);
    };
    auto stage = [&](int buf) {
#pragma unroll
        for (int it = 0; it < 2; it++) {
            uint32_t h0, l0, h1, l1;
            split2(pa[it].x, pa[it].y, h0, l0);
            split2(pa[it].z, pa[it].w, h1, l1);
            int base = am[it] * GASTR + aq[it] * 2;
            Ah[buf][base] = h0;  Ah[buf][base + 1] = h1;
            Al[buf][base] = l0;  Al[buf][base + 1] = l1;
        }
        uint32_t h[4], l[4];
        split2(pb0.x, pb1.x, h[0], l[0]);
        split2(pb0.y, pb1.y, h[1], l[1]);
        split2(pb0.z, pb1.z, h[2], l[2]);
        split2(pb0.w, pb1.w, h[3], l[3]);
        *(uint4*)&Bh[buf][bkp * GBSTR + bn0] = make_uint4(h[0], h[1], h[2], h[3]);
        *(uint4*)&Bl[buf][bkp * GBSTR + bn0] = make_uint4(l[0], l[1], l[2], l[3]);
    };

    prefetch(0);
    stage(0);
    __syncthreads();

    int buf = 0;
    for (int k0 = 0; k0 < K; k0 += 16) {
        const bool has_next = (k0 + 16) < K;
        if (has_next) prefetch(k0 + 16);

        uint32_t bh[4][2], bl[4][2];
#pragma unroll
        for (int nt = 0; nt < 4; nt++) {
            const int col = wn + nt * 8 + g;
            bh[nt][0] = Bh[buf][t * GBSTR + col];
            bh[nt][1] = Bh[buf][(t + 4) * GBSTR + col];
            bl[nt][0] = Bl[buf][t * GBSTR + col];
            bl[nt][1] = Bl[buf][(t + 4) * GBSTR + col];
        }
#pragma unroll
        for (int mt = 0; mt < 4; mt++) {
            const int r = wm + mt * 16 + g;
            uint32_t ah0 = Ah[buf][r * GASTR + t];
            uint32_t ah1 = Ah[buf][(r + 8) * GASTR + t];
            uint32_t ah2 = Ah[buf][r * GASTR + t + 4];
            uint32_t ah3 = Ah[buf][(r + 8) * GASTR + t + 4];
            uint32_t al0 = Al[buf][r * GASTR + t];
            uint32_t al1 = Al[buf][(r + 8) * GASTR + t];
            uint32_t al2 = Al[buf][r * GASTR + t + 4];
            uint32_t al3 = Al[buf][(r + 8) * GASTR + t + 4];
#pragma unroll
            for (int nt = 0; nt < 4; nt++) {
                mma_bf16(acc[mt][nt], ah0, ah1, ah2, ah3, bh[nt][0], bh[nt][1]);
                mma_bf16(acc[mt][nt], ah0, ah1, ah2, ah3, bl[nt][0], bl[nt][1]);
                mma_bf16(acc[mt][nt], al0, al1, al2, al3, bh[nt][0], bh[nt][1]);
            }
        }

        if (has_next) {
            stage(buf ^ 1);
            __syncthreads();
            buf ^= 1;
        }
    }

#pragma unroll
    for (int nt = 0; nt < 4; nt++) {
        const int col = bcol + wn + nt * 8 + 2 * t;
        const float2 bv = *(const float2*)(bias + col);
#pragma unroll
        for (int mt = 0; mt < 4; mt++) {
            const int row0 = brow + wm + mt * 16 + g;
            float v00 = acc[mt][nt][0] + bv.x, v01 = acc[mt][nt][1] + bv.y;
            float v10 = acc[mt][nt][2] + bv.x, v11 = acc[mt][nt][3] + bv.y;
            if (mode == 0) {
                *(float2*)(Cf + (size_t)row0 * N + col)       = make_float2(v00, v01);
                *(float2*)(Cf + (size_t)(row0 + 8) * N + col) = make_float2(v10, v11);
            } else {
                uint32_t h, l;
                size_t i0 = ((size_t)row0 * N + col) >> 1;
                split2(v00, v01, h, l);  Chi[i0] = h;  Clo[i0] = l;
                size_t i1 = ((size_t)(row0 + 8) * N + col) >> 1;
                split2(v10, v11, h, l);  Chi[i1] = h;  Clo[i1] = l;
            }
        }
    }
}

// ---------------------------------------------------------------------------
// Flash attention v3 (R9) + fused max|attn| reduction in epilogue.
// ---------------------------------------------------------------------------
#define FSTR 36
#define OFF_QL (128 * FSTR)
#define OFF_BUF (2 * 128 * FSTR)
#define BUF_SZ  (4 * 64 * FSTR)
#define PL_SZ   (64 * FSTR)
#define FL_SMEM ((OFF_BUF + 2 * BUF_SZ) * 4)   // 110592 bytes

__global__ __launch_bounds__(256, 2)
void flash_bf16x3(const uint32_t* __restrict__ qh,
                  const uint32_t* __restrict__ ql,
                  float* __restrict__ out)
{
    extern __shared__ uint32_t sm[];
    uint32_t* Qh = sm;
    uint32_t* Ql = sm + OFF_QL;
    const uint32_t sb = (uint32_t)__cvta_generic_to_shared(sm);

    const int qbx = gridDim.x - 1 - blockIdx.x;
    const int h   = blockIdx.y;
    const int b   = blockIdx.z;

    const int tid  = threadIdx.x;
    const int wid  = tid >> 5;
    const int lane = tid & 31;
    const int g = lane >> 2;
    const int t = lane & 3;

    const int qoff = h * 32;
    const int koff = 512 + h * 32;
    const int voff = 1024 + h * 32;

    const int wq = qbx * 128 + wid * 16;

#pragma unroll
    for (int it = 0; it < 16; it++) {
        int idx = tid + it * 256;
        int row = idx >> 5;
        int dp  = idx & 31;
        size_t gi = (size_t)(b * SEQ + qbx * 128 + row) * LD32 + qoff + dp;
        Qh[row * FSTR + dp] = qh[gi];
        Ql[row * FSTR + dp] = ql[gi];
    }

    const int crow = tid >> 3;
    const int cch  = tid & 7;
    auto issue_blk = [&](int jb, int buf) {
        const uint32_t base = sb + (uint32_t)((OFF_BUF + buf * BUF_SZ) * 4);
        const size_t trow = (size_t)(b * SEQ + jb * 64);
#pragma unroll
        for (int i = 0; i < 2; i++) {
            int row = crow + i * 32;
            uint32_t so = (uint32_t)(row * 144 + cch * 16);
            size_t gr = (trow + row) * LD32 + cch * 4;
            cp16(base + 0 * (PL_SZ * 4) + so, qh + gr + koff);
            cp16(base + 1 * (PL_SZ * 4) + so, ql + gr + koff);
            cp16(base + 2 * (PL_SZ * 4) + so, qh + gr + voff);
            cp16(base + 3 * (PL_SZ * 4) + so, ql + gr + voff);
        }
        CP_COMMIT();
    };

    const uint32_t qa   = sb + (uint32_t)((wid * 16 + (lane & 15)) * 144 +
                                          (lane >> 4) * 16);
    const uint32_t krow = (uint32_t)((lane & 7) + ((lane >> 4) & 1) * 8);
    const uint32_t kcol = (uint32_t)(((lane >> 3) & 1) * 16);
    const uint32_t vrow = (uint32_t)(lane & 15);
    const uint32_t vcol = (uint32_t)(((lane >> 4) & 1) * 16);

    float oa[8][4];
#pragma unroll
    for (int nt = 0; nt < 8; nt++)
#pragma unroll
        for (int r = 0; r < 4; r++) oa[nt][r] = 0.0f;
    float m0 = -1e30f, m1 = -1e30f, l0 = 0.0f, l1 = 0.0f;

    const int r0g = wq + g;
    const int r1g = wq + g + 8;
    const int nblocks = 2 * qbx + 2;

    issue_blk(0, 0);
    issue_blk(1, 1);

    for (int jb = 0; jb < nblocks; jb++) {
        if (jb + 1 < nblocks) CP_WAIT(1); else CP_WAIT(0);
        __syncthreads();

        if (jb * 64 <= wq + 15) {
            const uint32_t kbH = sb + (uint32_t)((OFF_BUF + (jb & 1) * BUF_SZ) * 4);
            const uint32_t kbL = kbH + PL_SZ * 4;
            const uint32_t vbH = kbL + PL_SZ * 4;
            const uint32_t vbL = vbH + PL_SZ * 4;

            float sc[8][4];
#pragma unroll
            for (int nt = 0; nt < 8; nt++)
#pragma unroll
                for (int r = 0; r < 4; r++) sc[nt][r] = 0.0f;

#pragma unroll
            for (int s = 0; s < 4; s++) {
                uint32_t q0, q1, q2, q3, p0, p1, p2, p3;
                ldsm4(q0, q1, q2, q3, qa + (uint32_t)(s * 32));
                ldsm4(p0, p1, p2, p3, qa + (uint32_t)(OFF_QL * 4 + s * 32));
#pragma unroll
                for (int np = 0; np < 4; np++) {
                    const uint32_t ro = (uint32_t)((np * 16 + krow) * 144) +
                                        (uint32_t)(s * 32) + kcol;
                    uint32_t kh0, kh1, kh2, kh3, kl0, kl1, kl2, kl3;
                    ldsm4(kh0, kh1, kh2, kh3, kbH + ro);
                    ldsm4(kl0, kl1, kl2, kl3, kbL + ro);
                    mma_bf16(sc[2 * np],     q0, q1, q2, q3, kh0, kh1);
                    mma_bf16(sc[2 * np],     q0, q1, q2, q3, kl0, kl1);
                    mma_bf16(sc[2 * np],     p0, p1, p2, p3, kh0, kh1);
                    mma_bf16(sc[2 * np + 1], q0, q1, q2, q3, kh2, kh3);
                    mma_bf16(sc[2 * np + 1], q0, q1, q2, q3, kl2, kl3);
                    mma_bf16(sc[2 * np + 1], p0, p1, p2, p3, kh2, kh3);
                }
            }

            if (jb * 64 + 63 > wq) {
#pragma unroll
                for (int nt = 0; nt < 8; nt++) {
                    int c = jb * 64 + nt * 8 + 2 * t;
                    if (c > r0g)     sc[nt][0] = -1e30f;
                    if (c + 1 > r0g) sc[nt][1] = -1e30f;
                    if (c > r1g)     sc[nt][2] = -1e30f;
                    if (c + 1 > r1g) sc[nt][3] = -1e30f;
                }
            }

            float mx0 = -1e30f, mx1 = -1e30f;
#pragma unroll
            for (int nt = 0; nt < 8; nt++) {
                mx0 = fmaxf(mx0, fmaxf(sc[nt][0], sc[nt][1]));
                mx1 = fmaxf(mx1, fmaxf(sc[nt][2], sc[nt][3]));
            }
#pragma unroll
            for (int off = 1; off <= 2; off <<= 1) {
                mx0 = fmaxf(mx0, __shfl_xor_sync(0xffffffffu, mx0, off));
                mx1 = fmaxf(mx1, __shfl_xor_sync(0xffffffffu, mx1, off));
            }
            float mn0 = fmaxf(m0, mx0), mn1 = fmaxf(m1, mx1);
            float corr0 = __expf(m0 - mn0), corr1 = __expf(m1 - mn1);
            float s0 = 0.0f, s1 = 0.0f;
#pragma unroll
            for (int nt = 0; nt < 8; nt++) {
                sc[nt][0] = __expf(sc[nt][0] - mn0);
                sc[nt][1] = __expf(sc[nt][1] - mn0);
                sc[nt][2] = __expf(sc[nt][2] - mn1);
                sc[nt][3] = __expf(sc[nt][3] - mn1);
                s0 += sc[nt][0] + sc[nt][1];
                s1 += sc[nt][2] + sc[nt][3];
            }
#pragma unroll
            for (int off = 1; off <= 2; off <<= 1) {
                s0 += __shfl_xor_sync(0xffffffffu, s0, off);
                s1 += __shfl_xor_sync(0xffffffffu, s1, off);
            }
            l0 = l0 * corr0 + s0;  m0 = mn0;
            l1 = l1 * corr1 + s1;  m1 = mn1;
#pragma unroll
            for (int nt = 0; nt < 8; nt++) {
                oa[nt][0] *= corr0;  oa[nt][1] *= corr0;
                oa[nt][2] *= corr1;  oa[nt][3] *= corr1;
            }

#pragma unroll
            for (int s = 0; s < 4; s++) {
                uint32_t ph[4], pl[4];
                split2(sc[2 * s][0],     sc[2 * s][1],     ph[0], pl[0]);
                split2(sc[2 * s][2],     sc[2 * s][3],     ph[1], pl[1]);
                split2(sc[2 * s + 1][0], sc[2 * s + 1][1], ph[2], pl[2]);
                split2(sc[2 * s + 1][2], sc[2 * s + 1][3], ph[3], pl[3]);
#pragma unroll
                for (int np = 0; np < 4; np++) {
                    const uint32_t ro = (uint32_t)((s * 16 + vrow) * 144) +
                                        (uint32_t)(np * 32) + vcol;
                    uint32_t vh0, vh1, vh2, vh3, vl0, vl1, vl2, vl3;
                    ldsm4t(vh0, vh1, vh2, vh3, vbH + ro);
                    ldsm4t(vl0, vl1, vl2, vl3, vbL + ro);
                    mma_bf16(oa[2 * np],     ph[0], ph[1], ph[2], ph[3], vh0, vh1);
                    mma_bf16(oa[2 * np],     ph[0], ph[1], ph[2], ph[3], vl0, vl1);
                    mma_bf16(oa[2 * np],     pl[0], pl[1], pl[2], pl[3], vh0, vh1);
                    mma_bf16(oa[2 * np + 1], ph[0], ph[1], ph[2], ph[3], vh2, vh3);
                    mma_bf16(oa[2 * np + 1], ph[0], ph[1], ph[2], ph[3], vl2, vl3);
                    mma_bf16(oa[2 * np + 1], pl[0], pl[1], pl[2], pl[3], vh2, vh3);
                }
            }
        }

        __syncthreads();
        if (jb + 2 < nblocks) issue_blk(jb + 2, jb & 1);
    }

    // epilogue: store + fused max|attn| reduction
    const float inv0 = 1.0f / l0, inv1 = 1.0f / l1;
    const size_t orow0 = (size_t)(b * SEQ + r0g) * HIDDEN + h * HDIM;
    const size_t orow1 = (size_t)(b * SEQ + r1g) * HIDDEN + h * HDIM;
    float lmax = 0.0f;
#pragma unroll
    for (int nt = 0; nt < 8; nt++) {
        const int d = nt * 8 + 2 * t;
        float2 o0 = make_float2(oa[nt][0] * inv0, oa[nt][1] * inv0);
        float2 o1 = make_float2(oa[nt][2] * inv1, oa[nt][3] * inv1);
        *(float2*)(out + orow0 + d) = o0;
        *(float2*)(out + orow1 + d) = o1;
        lmax = fmaxf(lmax, fmaxf(fmaxf(fabsf(o0.x), fabsf(o0.y)),
                                 fmaxf(fabsf(o1.x), fabsf(o1.y))));
    }
#pragma unroll
    for (int off = 16; off >= 1; off >>= 1)
        lmax = fmaxf(lmax, __shfl_xor_sync(0xffffffffu, lmax, off));
    if (lane == 0)
        atomicMax(&g_maxA, __float_as_uint(lmax));
}

// ---------------------------------------------------------------------------
// int8 2-digit GEMM + bias (R7 kernel, verbatim)
// ---------------------------------------------------------------------------
#define IA_PL 6144
#define IB_PL 3072
#define ISTG (2 * IA_PL + 2 * IB_PL)
#define INST 4
#define INT8_SMEM (INST * ISTG)      // 73728

__global__ __launch_bounds__(256, 2)
void gemm_int8(const int8_t* __restrict__ A1, const int8_t* __restrict__ A2,
               const int8_t* __restrict__ W1, const int8_t* __restrict__ W2,
               const float* __restrict__ bias, float* __restrict__ C,
               int M, int N, int K)
{
    extern __shared__ uint32_t smem[];
    const uint32_t sb = (uint32_t)__cvta_generic_to_shared(smem);

    const int tid  = threadIdx.x;
    const int warp = tid >> 5;
    const int lane = tid & 31;
    const int g = lane >> 2;
    const int t = lane & 3;
    const int wm = (warp >> 1) * 32;
    const int wn = (warp & 1) * 32;
    const int brow = blockIdx.y * 128;
    const int bcol = blockIdx.x * 64;

    const int arow = tid >> 1, ahalf = tid & 1;
    const int wrow = tid >> 2, whalf = (tid >> 1) & 1, wpl = tid & 1;
    const int8_t* gA[2] = { A1 + (size_t)(brow + arow) * K + ahalf * 16,
                            A2 + (size_t)(brow + arow) * K + ahalf * 16 };
    const int8_t* gW   = (wpl ? W2 : W1) + (size_t)(bcol + wrow) * K + whalf * 16;

    auto issue_chunk = [&](int c) {
        const uint32_t base = sb + (uint32_t)((c & (INST - 1)) * ISTG);
        const int k0 = c * 32;
        cp16(base + 0 * IA_PL + arow * 48 + ahalf * 16, gA[0] + k0);
        cp16(base + 1 * IA_PL + arow * 48 + ahalf * 16, gA[1] + k0);
        cp16(base + 2 * IA_PL + wpl * IB_PL + wrow * 48 + whalf * 16, gW + k0);
        CP_COMMIT();
    };

    const int laA = (lane & 7) + ((lane >> 3) & 1) * 8;
    const uint32_t kaA = (uint32_t)(((lane >> 4) & 1) * 16);
    const int laB = (lane & 7) + ((lane >> 4) & 1) * 8;
    const uint32_t kaB = (uint32_t)(((lane >> 3) & 1) * 16);

    int acc1[2][4][4], acc2[2][4][4];
#pragma unroll
    for (int mt = 0; mt < 2; mt++)
#pragma unroll
        for (int nt = 0; nt < 4; nt++)
#pragma unroll
            for (int r = 0; r < 4; r++) { acc1[mt][nt][r] = 0; acc2[mt][nt][r] = 0; }

    const int NC = K / 32;
#pragma unroll
    for (int s = 0; s < INST - 1; s++) issue_chunk(s);

    for (int c = 0; c < NC; c++) {
        CP_WAIT(INST - 2);
        __syncthreads();
        if (c + INST - 1 < NC) issue_chunk(c + INST - 1);

        const uint32_t base = sb + (uint32_t)((c & (INST - 1)) * ISTG);
        uint32_t b1[4][2], b2[4][2];
#pragma unroll
        for (int np = 0; np < 2; np++) {
            const uint32_t ro = (uint32_t)((wn + np * 16 + laB) * 48) + kaB;
            ldsm4(b1[2 * np][0], b1[2 * np][1], b1[2 * np + 1][0], b1[2 * np + 1][1],
                  base + 2 * IA_PL + ro);
            ldsm4(b2[2 * np][0], b2[2 * np][1], b2[2 * np + 1][0], b2[2 * np + 1][1],
                  base + 2 * IA_PL + IB_PL + ro);
        }
#pragma unroll
        for (int mt = 0; mt < 2; mt++) {
            const uint32_t ro = (uint32_t)((wm + mt * 16 + laA) * 48) + kaA;
            uint32_t a1f[4], a2f[4];
            ldsm4(a1f[0], a1f[1], a1f[2], a1f[3], base + ro);
            ldsm4(a2f[0], a2f[1], a2f[2], a2f[3], base + IA_PL + ro);
#pragma unroll
            for (int nt = 0; nt < 4; nt++) {
                mma_s8(acc1[mt][nt], a1f[0], a1f[1], a1f[2], a1f[3],
                       b1[nt][0], b1[nt][1]);
                mma_s8(acc2[mt][nt], a1f[0], a1f[1], a1f[2], a1f[3],
                       b2[nt][0], b2[nt][1]);
                mma_s8(acc2[mt][nt], a2f[0], a2f[1], a2f[2], a2f[3],
                       b1[nt][0], b1[nt][1]);
            }
        }
    }

    const float maxA = fmaxf(__uint_as_float(g_maxA), 1e-30f);
    const float maxW = fmaxf(__uint_as_float(g_maxW), 1e-30f);
    const float inv = (maxA * maxW) / (32512.0f * 32512.0f);

#pragma unroll
    for (int nt = 0; nt < 4; nt++) {
        const int col = bcol + wn + nt * 8 + 2 * t;
        const float2 bv = *(const float2*)(bias + col);
#pragma unroll
        for (int mt = 0; mt < 2; mt++) {
            const int row0 = brow + wm + mt * 16 + g;
            float2 o0, o1;
            o0.x = (65536.0f * (float)acc1[mt][nt][0] + 256.0f * (float)acc2[mt][nt][0]) * inv + bv.x;
            o0.y = (65536.0f * (float)acc1[mt][nt][1] + 256.0f * (float)acc2[mt][nt][1]) * inv + bv.y;
            o1.x = (65536.0f * (float)acc1[mt][nt][2] + 256.0f * (float)acc2[mt][nt][2]) * inv + bv.x;
            o1.y = (65536.0f * (float)acc1[mt][nt][3] + 256.0f * (float)acc2[mt][nt][3]) * inv + bv.y;
            *(float2*)(C + (size_t)row0 * N + col)       = o0;
            *(float2*)(C + (size_t)(row0 + 8) * N + col) = o1;
        }
    }
}

// ---------------------------------------------------------------------------
// Launch
// ---------------------------------------------------------------------------
extern "C" void kernel_launch(void* const* d_in, const int* in_sizes, int n_in,
                              void* d_out, int out_size)
{
    const float* hidden = (const float*)d_in[0];
    const float* w_attn = (const float*)d_in[1];
    const float* b_attn = (const float*)d_in[2];
    const float* w_proj = (const float*)d_in[3];
    const float* b_proj = (const float*)d_in[4];
    float* out = (float*)d_out;

    uint32_t *qh, *ql;
    float* attn;
    int8_t *a1, *a2, *w1, *w2;
    unsigned* mW;
    cudaGetSymbolAddress((void**)&qh, g_qh);
    cudaGetSymbolAddress((void**)&ql, g_ql);
    cudaGetSymbolAddress((void**)&attn, g_attn);
    cudaGetSymbolAddress((void**)&a1, g_a1);
    cudaGetSymbolAddress((void**)&a2, g_a2);
    cudaGetSymbolAddress((void**)&w1, g_w1);
    cudaGetSymbolAddress((void**)&w2, g_w2);
    cudaGetSymbolAddress((void**)&mW, g_maxW);

    static bool attr_set = false;
    if (!attr_set) {
        cudaFuncSetAttribute(flash_bf16x3,
                             cudaFuncAttributeMaxDynamicSharedMemorySize, FL_SMEM);
        cudaFuncSetAttribute(gemm_int8,
                             cudaFuncAttributeMaxDynamicSharedMemorySize, INT8_SMEM);
        attr_set = true;
    }

    // 0) w_proj max + transpose/quantize (small, before the main chain)
    maxabs_kernel<<<256, 256>>>(w_proj, HIDDEN * HIDDEN, mW);
    {
        dim3 gp(HIDDEN / 32, HIDDEN / 64);
        transpose_quant_kernel<<<gp, 256>>>(w_proj, w1, w2, HIDDEN, HIDDEN);
    }
    // 1) QKV projection -> split bf16 planes (at HMMA cap)
    {
        dim3 grid(QKV_N / 128, M_TOK / 128);
        gemm_bf16x3<<<grid, 256>>>(hidden, w_attn, b_attn,
                                   nullptr, qh, ql,
                                   M_TOK, QKV_N, HIDDEN, 1);
    }
    // 2) flash attention v3 -> fp32 attn + g_maxA (fused reduction)
    {
        dim3 grid(SEQ / 128, NHEAD, BATCH);
        flash_bf16x3<<<grid, 256, FL_SMEM>>>(qh, ql, attn);
    }
    // 3) quantize attn to int8 digits
    {
        const int n = M_TOK * HIDDEN;
        quant_attn_kernel<<<(n + 255) / 256, 256>>>(attn, a1, a2, n);
    }
    // 4) output projection via int8 IMMA (2x MACs/instr)
    {
        dim3 grid(HIDDEN / 64, M_TOK / 128);
        gemm_int8<<<grid, 256, INT8_SMEM>>>(a1, a2, w1, w2, b_proj, out,
                                            M_TOK, HIDDEN, HIDDEN);
    }
}

// round 11
// speedup vs baseline: 1.2532x; 1.0623x over previous
#include <cuda_runtime.h>
#include <cuda_bf16.h>
#include <cuda_fp16.h>
#include <math.h>
#include <stdint.h>

// ---------------------------------------------------------------------------
// Problem constants
// ---------------------------------------------------------------------------
#define BATCH 2
#define SEQ 2048
#define HIDDEN 1024
#define NHEAD 16
#define HDIM 64
#define M_TOK (BATCH * SEQ)          // 4096
#define QKV_N (3 * HIDDEN)           // 3072
#define LD32 (QKV_N / 2)             // 1536 u32 per token row (qkv planes)

// Scratch (__device__ globals per allocation rules)
__device__ uint32_t g_qh[(size_t)M_TOK * LD32];      // qkv hi plane (V range: fp16)
__device__ uint32_t g_ql[(size_t)M_TOK * LD32];      // qkv lo plane
__device__ float    g_attn[(size_t)M_TOK * HIDDEN];  // attention output fp32
__device__ int8_t   g_a1[(size_t)M_TOK * HIDDEN];    // attn digit1
__device__ int8_t   g_a2[(size_t)M_TOK * HIDDEN];    // attn digit2
__device__ int8_t   g_w1[(size_t)HIDDEN * HIDDEN];   // w_proj^T digit1 [n][k]
__device__ int8_t   g_w2[(size_t)HIDDEN * HIDDEN];   // w_proj^T digit2
__device__ unsigned g_maxA;                          // max|attn| (float bits)
__device__ unsigned g_maxW;                          // max|w_proj|

// ---------------------------------------------------------------------------
// Helpers
// ---------------------------------------------------------------------------
__device__ __forceinline__ void split2(float x, float y,
                                       uint32_t& hi, uint32_t& lo) {
    __nv_bfloat162 h = __floats2bfloat162_rn(x, y);
    float2 hf = __bfloat1622float2(h);
    __nv_bfloat162 l = __floats2bfloat162_rn(x - hf.x, y - hf.y);
    hi = *reinterpret_cast<uint32_t*>(&h);
    lo = *reinterpret_cast<uint32_t*>(&l);
}

// fp16 hi/lo split (pair reproduces fp32 to ~2^-23)
__device__ __forceinline__ void split2h(float x, float y,
                                        uint32_t& hi, uint32_t& lo) {
    __half2 h = __floats2half2_rn(x, y);
    float2 hf = __half22float2(h);
    __half2 l = __floats2half2_rn(x - hf.x, y - hf.y);
    hi = *reinterpret_cast<uint32_t*>(&h);
    lo = *reinterpret_cast<uint32_t*>(&l);
}

__device__ __forceinline__ uint32_t pack_h2(float x, float y) {
    __half2 h = __floats2half2_rn(x, y);
    return *reinterpret_cast<uint32_t*>(&h);
}

__device__ __forceinline__ void mma_bf16(float* c, uint32_t a0, uint32_t a1,
                                         uint32_t a2, uint32_t a3,
                                         uint32_t b0, uint32_t b1) {
    asm volatile(
        "mma.sync.aligned.m16n8k16.row.col.f32.bf16.bf16.f32 "
        "{%0,%1,%2,%3}, {%4,%5,%6,%7}, {%8,%9}, {%0,%1,%2,%3};"
        : "+f"(c[0]), "+f"(c[1]), "+f"(c[2]), "+f"(c[3])
        : "r"(a0), "r"(a1), "r"(a2), "r"(a3), "r"(b0), "r"(b1));
}

__device__ __forceinline__ void mma_f16(float* c, uint32_t a0, uint32_t a1,
                                        uint32_t a2, uint32_t a3,
                                        uint32_t b0, uint32_t b1) {
    asm volatile(
        "mma.sync.aligned.m16n8k16.row.col.f32.f16.f16.f32 "
        "{%0,%1,%2,%3}, {%4,%5,%6,%7}, {%8,%9}, {%0,%1,%2,%3};"
        : "+f"(c[0]), "+f"(c[1]), "+f"(c[2]), "+f"(c[3])
        : "r"(a0), "r"(a1), "r"(a2), "r"(a3), "r"(b0), "r"(b1));
}

__device__ __forceinline__ void mma_s8(int* c, uint32_t a0, uint32_t a1,
                                       uint32_t a2, uint32_t a3,
                                       uint32_t b0, uint32_t b1) {
    asm volatile(
        "mma.sync.aligned.m16n8k32.row.col.s32.s8.s8.s32 "
        "{%0,%1,%2,%3}, {%4,%5,%6,%7}, {%8,%9}, {%0,%1,%2,%3};"
        : "+r"(c[0]), "+r"(c[1]), "+r"(c[2]), "+r"(c[3])
        : "r"(a0), "r"(a1), "r"(a2), "r"(a3), "r"(b0), "r"(b1));
}

__device__ __forceinline__ void ldsm4(uint32_t& r0, uint32_t& r1,
                                      uint32_t& r2, uint32_t& r3, uint32_t a) {
    asm volatile("ldmatrix.sync.aligned.m8n8.x4.shared.b16 {%0,%1,%2,%3}, [%4];"
                 : "=r"(r0), "=r"(r1), "=r"(r2), "=r"(r3) : "r"(a));
}

__device__ __forceinline__ void ldsm4t(uint32_t& r0, uint32_t& r1,
                                       uint32_t& r2, uint32_t& r3, uint32_t a) {
    asm volatile("ldmatrix.sync.aligned.m8n8.x4.trans.shared.b16 {%0,%1,%2,%3}, [%4];"
                 : "=r"(r0), "=r"(r1), "=r"(r2), "=r"(r3) : "r"(a));
}

__device__ __forceinline__ void cp16(uint32_t smem, const void* gmem) {
    asm volatile("cp.async.ca.shared.global [%0], [%1], 16;"
                 :: "r"(smem), "l"(gmem));
}
#define CP_COMMIT() asm volatile("cp.async.commit_group;" ::: "memory")
#define CP_WAIT(n)  asm volatile("cp.async.wait_group %0;" :: "n"(n) : "memory")

// quantize x (|x| <= max) to q1*256 + q2 with S = 32512/max
__device__ __forceinline__ void quant2(float x, float S, int8_t& d1, int8_t& d2) {
    int q = __float2int_rn(x * S);
    int q1 = (q + 128) >> 8;
    d1 = (int8_t)q1;
    d2 = (int8_t)(q - (q1 << 8));
}

// ---------------------------------------------------------------------------
// max-abs reduction (for w_proj)
// ---------------------------------------------------------------------------
__global__ __launch_bounds__(256)
void maxabs_kernel(const float* __restrict__ x, int n, unsigned* __restrict__ out)
{
    float m = 0.0f;
    for (int i = blockIdx.x * 256 + threadIdx.x; i < n; i += gridDim.x * 256)
        m = fmaxf(m, fabsf(x[i]));
#pragma unroll
    for (int off = 16; off >= 1; off >>= 1)
        m = fmaxf(m, __shfl_xor_sync(0xffffffffu, m, off));
    if ((threadIdx.x & 31) == 0)
        atomicMax(out, __float_as_uint(m));
}

// ---------------------------------------------------------------------------
// quantize attn fp32 -> digit planes (maxA produced by flash epilogue)
// ---------------------------------------------------------------------------
__global__ __launch_bounds__(256)
void quant_attn_kernel(const float* __restrict__ x,
                       int8_t* __restrict__ d1, int8_t* __restrict__ d2, int n)
{
    const float maxv = fmaxf(__uint_as_float(g_maxA), 1e-30f);
    const float S = 32512.0f / maxv;
    int i = blockIdx.x * 256 + threadIdx.x;
    if (i < n) quant2(x[i], S, d1[i], d2[i]);
}

// ---------------------------------------------------------------------------
// transpose + quantize  W[K][N] -> digit planes [N][K]
// ---------------------------------------------------------------------------
__global__ __launch_bounds__(256)
void transpose_quant_kernel(const float* __restrict__ W,
                            int8_t* __restrict__ d1, int8_t* __restrict__ d2,
                            int K, int N)
{
    __shared__ float s[64][33];
    const int tid = threadIdx.x;
    const int k0 = blockIdx.y * 64;
    const int n0 = blockIdx.x * 32;
    const float maxv = fmaxf(__uint_as_float(g_maxW), 1e-30f);
    const float S = 32512.0f / maxv;

#pragma unroll
    for (int i = 0; i < 8; i++) {
        int idx = tid + i * 256;
        int nl = idx & 31;
        int kl = idx >> 5;
        s[kl][nl] = W[(size_t)(k0 + kl) * N + n0 + nl];
    }
    __syncthreads();

#pragma unroll
    for (int i = 0; i < 8; i++) {
        int idx = tid + i * 256;
        int kl = idx & 63;
        int nl = idx >> 6;
        size_t o = (size_t)(n0 + nl) * K + k0 + kl;
        quant2(s[kl][nl], S, d1[o], d2[o]);
    }
}

// ---------------------------------------------------------------------------
// bf16x3 GEMM + bias (at the HMMA cap): C = A[M,K] @ B[K,N] + bias
// mode 0: fp32 C. mode 1: split planes (bf16 for cols<2048, fp16 for V cols).
// ---------------------------------------------------------------------------
#define GASTR 12
#define GBSTR 136

__global__ __launch_bounds__(256)
void gemm_bf16x3(const float* __restrict__ A, const float* __restrict__ B,
                 const float* __restrict__ bias,
                 float* __restrict__ Cf,
                 uint32_t* __restrict__ Chi, uint32_t* __restrict__ Clo,
                 int M, int N, int K, int mode)
{
    __shared__ uint32_t Ah[2][128 * GASTR], Al[2][128 * GASTR];
    __shared__ uint32_t Bh[2][8 * GBSTR],  Bl[2][8 * GBSTR];

    const int tid  = threadIdx.x;
    const int warp = tid >> 5;
    const int lane = tid & 31;
    const int g = lane >> 2;
    const int t = lane & 3;
    const int wm = (warp >> 2) * 64;
    const int wn = (warp & 3) * 32;
    const int brow = blockIdx.y * 128;
    const int bcol = blockIdx.x * 128;

    float acc[4][4][4];
#pragma unroll
    for (int mt = 0; mt < 4; mt++)
#pragma unroll
        for (int nt = 0; nt < 4; nt++)
#pragma unroll
            for (int r = 0; r < 4; r++) acc[mt][nt][r] = 0.0f;

    const int am[2] = { (tid + 0) >> 2, (tid + 256) >> 2 };
    const int aq[2] = { (tid + 0) & 3,  (tid + 256) & 3 };
    const int bkp   = tid >> 5;
    const int bn0   = (tid & 31) * 4;

    float4 pa[2], pb0, pb1;

    auto prefetch = [&](int k0) {
#pragma unroll
        for (int it = 0; it < 2; it++)
            pa[it] = *(const float4*)(A + (size_t)(brow + am[it]) * K + k0 + aq[it] * 4);
        pb0 = *(const float4*)(B + (size_t)(k0 + 2 * bkp) * N + bcol + bn0);
        pb1 = *(const float4*)(B + (size_t)(k0 + 2 * bkp + 1) * N + bcol + bn0);
    };
    auto stage = [&](int buf) {
#pragma unroll
        for (int it = 0; it < 2; it++) {
            uint32_t h0, l0, h1, l1;
            split2(pa[it].x, pa[it].y, h0, l0);
            split2(pa[it].z, pa[it].w, h1, l1);
            int base = am[it] * GASTR + aq[it] * 2;
            Ah[buf][base] = h0;  Ah[buf][base + 1] = h1;
            Al[buf][base] = l0;  Al[buf][base + 1] = l1;
        }
        uint32_t h[4], l[4];
        split2(pb0.x, pb1.x, h[0], l[0]);
        split2(pb0.y, pb1.y, h[1], l[1]);
        split2(pb0.z, pb1.z, h[2], l[2]);
        split2(pb0.w, pb1.w, h[3], l[3]);
        *(uint4*)&Bh[buf][bkp * GBSTR + bn0] = make_uint4(h[0], h[1], h[2], h[3]);
        *(uint4*)&Bl[buf][bkp * GBSTR + bn0] = make_uint4(l[0], l[1], l[2], l[3]);
    };

    prefetch(0);
    stage(0);
    __syncthreads();

    int buf = 0;
    for (int k0 = 0; k0 < K; k0 += 16) {
        const bool has_next = (k0 + 16) < K;
        if (has_next) prefetch(k0 + 16);

        uint32_t bh[4][2], bl[4][2];
#pragma unroll
        for (int nt = 0; nt < 4; nt++) {
            const int col = wn + nt * 8 + g;
            bh[nt][0] = Bh[buf][t * GBSTR + col];
            bh[nt][1] = Bh[buf][(t + 4) * GBSTR + col];
            bl[nt][0] = Bl[buf][t * GBSTR + col];
            bl[nt][1] = Bl[buf][(t + 4) * GBSTR + col];
        }
#pragma unroll
        for (int mt = 0; mt < 4; mt++) {
            const int r = wm + mt * 16 + g;
            uint32_t ah0 = Ah[buf][r * GASTR + t];
            uint32_t ah1 = Ah[buf][(r + 8) * GASTR + t];
            uint32_t ah2 = Ah[buf][r * GASTR + t + 4];
            uint32_t ah3 = Ah[buf][(r + 8) * GASTR + t + 4];
            uint32_t al0 = Al[buf][r * GASTR + t];
            uint32_t al1 = Al[buf][(r + 8) * GASTR + t];
            uint32_t al2 = Al[buf][r * GASTR + t + 4];
            uint32_t al3 = Al[buf][(r + 8) * GASTR + t + 4];
#pragma unroll
            for (int nt = 0; nt < 4; nt++) {
                mma_bf16(acc[mt][nt], ah0, ah1, ah2, ah3, bh[nt][0], bh[nt][1]);
                mma_bf16(acc[mt][nt], ah0, ah1, ah2, ah3, bl[nt][0], bl[nt][1]);
                mma_bf16(acc[mt][nt], al0, al1, al2, al3, bh[nt][0], bh[nt][1]);
            }
        }

        if (has_next) {
            stage(buf ^ 1);
            __syncthreads();
            buf ^= 1;
        }
    }

    const bool vregion = (bcol >= 2 * HIDDEN);   // V columns -> fp16 planes
#pragma unroll
    for (int nt = 0; nt < 4; nt++) {
        const int col = bcol + wn + nt * 8 + 2 * t;
        const float2 bv = *(const float2*)(bias + col);
#pragma unroll
        for (int mt = 0; mt < 4; mt++) {
            const int row0 = brow + wm + mt * 16 + g;
            float v00 = acc[mt][nt][0] + bv.x, v01 = acc[mt][nt][1] + bv.y;
            float v10 = acc[mt][nt][2] + bv.x, v11 = acc[mt][nt][3] + bv.y;
            if (mode == 0) {
                *(float2*)(Cf + (size_t)row0 * N + col)       = make_float2(v00, v01);
                *(float2*)(Cf + (size_t)(row0 + 8) * N + col) = make_float2(v10, v11);
            } else {
                uint32_t h, l;
                size_t i0 = ((size_t)row0 * N + col) >> 1;
                size_t i1 = ((size_t)(row0 + 8) * N + col) >> 1;
                if (vregion) {
                    split2h(v00, v01, h, l);  Chi[i0] = h;  Clo[i0] = l;
                    split2h(v10, v11, h, l);  Chi[i1] = h;  Clo[i1] = l;
                } else {
                    split2(v00, v01, h, l);   Chi[i0] = h;  Clo[i0] = l;
                    split2(v10, v11, h, l);   Chi[i1] = h;  Clo[i1] = l;
                }
            }
        }
    }
}

// ---------------------------------------------------------------------------
// Flash attention v4: QK^T bf16x3, PV fp16 2-term (P single fp16, V fp16 pair).
// Fused block-level max|attn| (one atomic per CTA).
// ---------------------------------------------------------------------------
#define FSTR 36
#define OFF_QL (128 * FSTR)
#define OFF_BUF (2 * 128 * FSTR)
#define BUF_SZ  (4 * 64 * FSTR)
#define PL_SZ   (64 * FSTR)
#define FL_SMEM ((OFF_BUF + 2 * BUF_SZ) * 4)   // 110592 bytes

__global__ __launch_bounds__(256, 2)
void flash_bf16x3(const uint32_t* __restrict__ qh,
                  const uint32_t* __restrict__ ql,
                  float* __restrict__ out)
{
    extern __shared__ uint32_t sm[];
    uint32_t* Qh = sm;
    uint32_t* Ql = sm + OFF_QL;
    const uint32_t sb = (uint32_t)__cvta_generic_to_shared(sm);

    const int qbx = gridDim.x - 1 - blockIdx.x;
    const int h   = blockIdx.y;
    const int b   = blockIdx.z;

    const int tid  = threadIdx.x;
    const int wid  = tid >> 5;
    const int lane = tid & 31;
    const int g = lane >> 2;
    const int t = lane & 3;

    const int qoff = h * 32;
    const int koff = 512 + h * 32;
    const int voff = 1024 + h * 32;

    const int wq = qbx * 128 + wid * 16;

#pragma unroll
    for (int it = 0; it < 16; it++) {
        int idx = tid + it * 256;
        int row = idx >> 5;
        int dp  = idx & 31;
        size_t gi = (size_t)(b * SEQ + qbx * 128 + row) * LD32 + qoff + dp;
        Qh[row * FSTR + dp] = qh[gi];
        Ql[row * FSTR + dp] = ql[gi];
    }

    const int crow = tid >> 3;
    const int cch  = tid & 7;
    auto issue_blk = [&](int jb, int buf) {
        const uint32_t base = sb + (uint32_t)((OFF_BUF + buf * BUF_SZ) * 4);
        const size_t trow = (size_t)(b * SEQ + jb * 64);
#pragma unroll
        for (int i = 0; i < 2; i++) {
            int row = crow + i * 32;
            uint32_t so = (uint32_t)(row * 144 + cch * 16);
            size_t gr = (trow + row) * LD32 + cch * 4;
            cp16(base + 0 * (PL_SZ * 4) + so, qh + gr + koff);
            cp16(base + 1 * (PL_SZ * 4) + so, ql + gr + koff);
            cp16(base + 2 * (PL_SZ * 4) + so, qh + gr + voff);
            cp16(base + 3 * (PL_SZ * 4) + so, ql + gr + voff);
        }
        CP_COMMIT();
    };

    const uint32_t qa   = sb + (uint32_t)((wid * 16 + (lane & 15)) * 144 +
                                          (lane >> 4) * 16);
    const uint32_t krow = (uint32_t)((lane & 7) + ((lane >> 4) & 1) * 8);
    const uint32_t kcol = (uint32_t)(((lane >> 3) & 1) * 16);
    const uint32_t vrow = (uint32_t)(lane & 15);
    const uint32_t vcol = (uint32_t)(((lane >> 4) & 1) * 16);

    float oa[8][4];
#pragma unroll
    for (int nt = 0; nt < 8; nt++)
#pragma unroll
        for (int r = 0; r < 4; r++) oa[nt][r] = 0.0f;
    float m0 = -1e30f, m1 = -1e30f, l0 = 0.0f, l1 = 0.0f;

    const int r0g = wq + g;
    const int r1g = wq + g + 8;
    const int nblocks = 2 * qbx + 2;

    issue_blk(0, 0);
    issue_blk(1, 1);

    for (int jb = 0; jb < nblocks; jb++) {
        if (jb + 1 < nblocks) CP_WAIT(1); else CP_WAIT(0);
        __syncthreads();

        if (jb * 64 <= wq + 15) {
            const uint32_t kbH = sb + (uint32_t)((OFF_BUF + (jb & 1) * BUF_SZ) * 4);
            const uint32_t kbL = kbH + PL_SZ * 4;
            const uint32_t vbH = kbL + PL_SZ * 4;
            const uint32_t vbL = vbH + PL_SZ * 4;

            float sc[8][4];
#pragma unroll
            for (int nt = 0; nt < 8; nt++)
#pragma unroll
                for (int r = 0; r < 4; r++) sc[nt][r] = 0.0f;

#pragma unroll
            for (int s = 0; s < 4; s++) {
                uint32_t q0, q1, q2, q3, p0, p1, p2, p3;
                ldsm4(q0, q1, q2, q3, qa + (uint32_t)(s * 32));
                ldsm4(p0, p1, p2, p3, qa + (uint32_t)(OFF_QL * 4 + s * 32));
#pragma unroll
                for (int np = 0; np < 4; np++) {
                    const uint32_t ro = (uint32_t)((np * 16 + krow) * 144) +
                                        (uint32_t)(s * 32) + kcol;
                    uint32_t kh0, kh1, kh2, kh3, kl0, kl1, kl2, kl3;
                    ldsm4(kh0, kh1, kh2, kh3, kbH + ro);
                    ldsm4(kl0, kl1, kl2, kl3, kbL + ro);
                    mma_bf16(sc[2 * np],     q0, q1, q2, q3, kh0, kh1);
                    mma_bf16(sc[2 * np],     q0, q1, q2, q3, kl0, kl1);
                    mma_bf16(sc[2 * np],     p0, p1, p2, p3, kh0, kh1);
                    mma_bf16(sc[2 * np + 1], q0, q1, q2, q3, kh2, kh3);
                    mma_bf16(sc[2 * np + 1], q0, q1, q2, q3, kl2, kl3);
                    mma_bf16(sc[2 * np + 1], p0, p1, p2, p3, kh2, kh3);
                }
            }

            if (jb * 64 + 63 > wq) {
#pragma unroll
                for (int nt = 0; nt < 8; nt++) {
                    int c = jb * 64 + nt * 8 + 2 * t;
                    if (c > r0g)     sc[nt][0] = -1e30f;
                    if (c + 1 > r0g) sc[nt][1] = -1e30f;
                    if (c > r1g)     sc[nt][2] = -1e30f;
                    if (c + 1 > r1g) sc[nt][3] = -1e30f;
                }
            }

            float mx0 = -1e30f, mx1 = -1e30f;
#pragma unroll
            for (int nt = 0; nt < 8; nt++) {
                mx0 = fmaxf(mx0, fmaxf(sc[nt][0], sc[nt][1]));
                mx1 = fmaxf(mx1, fmaxf(sc[nt][2], sc[nt][3]));
            }
#pragma unroll
            for (int off = 1; off <= 2; off <<= 1) {
                mx0 = fmaxf(mx0, __shfl_xor_sync(0xffffffffu, mx0, off));
                mx1 = fmaxf(mx1, __shfl_xor_sync(0xffffffffu, mx1, off));
            }
            float mn0 = fmaxf(m0, mx0), mn1 = fmaxf(m1, mx1);
            float corr0 = __expf(m0 - mn0), corr1 = __expf(m1 - mn1);
            float s0 = 0.0f, s1 = 0.0f;
#pragma unroll
            for (int nt = 0; nt < 8; nt++) {
                sc[nt][0] = __expf(sc[nt][0] - mn0);
                sc[nt][1] = __expf(sc[nt][1] - mn0);
                sc[nt][2] = __expf(sc[nt][2] - mn1);
                sc[nt][3] = __expf(sc[nt][3] - mn1);
                s0 += sc[nt][0] + sc[nt][1];
                s1 += sc[nt][2] + sc[nt][3];
            }
#pragma unroll
            for (int off = 1; off <= 2; off <<= 1) {
                s0 += __shfl_xor_sync(0xffffffffu, s0, off);
                s1 += __shfl_xor_sync(0xffffffffu, s1, off);
            }
            l0 = l0 * corr0 + s0;  m0 = mn0;
            l1 = l1 * corr1 + s1;  m1 = mn1;
#pragma unroll
            for (int nt = 0; nt < 8; nt++) {
                oa[nt][0] *= corr0;  oa[nt][1] *= corr0;
                oa[nt][2] *= corr1;  oa[nt][3] *= corr1;
            }

            // --- O += P V : P single fp16, V fp16 hi/lo (2 mma terms) ---
#pragma unroll
            for (int s = 0; s < 4; s++) {
                uint32_t ph[4];
                ph[0] = pack_h2(sc[2 * s][0],     sc[2 * s][1]);
                ph[1] = pack_h2(sc[2 * s][2],     sc[2 * s][3]);
                ph[2] = pack_h2(sc[2 * s + 1][0], sc[2 * s + 1][1]);
                ph[3] = pack_h2(sc[2 * s + 1][2], sc[2 * s + 1][3]);
#pragma unroll
                for (int np = 0; np < 4; np++) {
                    const uint32_t ro = (uint32_t)((s * 16 + vrow) * 144) +
                                        (uint32_t)(np * 32) + vcol;
                    uint32_t vh0, vh1, vh2, vh3, vl0, vl1, vl2, vl3;
                    ldsm4t(vh0, vh1, vh2, vh3, vbH + ro);
                    ldsm4t(vl0, vl1, vl2, vl3, vbL + ro);
                    mma_f16(oa[2 * np],     ph[0], ph[1], ph[2], ph[3], vh0, vh1);
                    mma_f16(oa[2 * np],     ph[0], ph[1], ph[2], ph[3], vl0, vl1);
                    mma_f16(oa[2 * np + 1], ph[0], ph[1], ph[2], ph[3], vh2, vh3);
                    mma_f16(oa[2 * np + 1], ph[0], ph[1], ph[2], ph[3], vl2, vl3);
                }
            }
        }

        __syncthreads();
        if (jb + 2 < nblocks) issue_blk(jb + 2, jb & 1);
    }

    // epilogue: store + block-level max|attn| (one atomic per CTA)
    const float inv0 = 1.0f / l0, inv1 = 1.0f / l1;
    const size_t orow0 = (size_t)(b * SEQ + r0g) * HIDDEN + h * HDIM;
    const size_t orow1 = (size_t)(b * SEQ + r1g) * HIDDEN + h * HDIM;
    float lmax = 0.0f;
#pragma unroll
    for (int nt = 0; nt < 8; nt++) {
        const int d = nt * 8 + 2 * t;
        float2 o0 = make_float2(oa[nt][0] * inv0, oa[nt][1] * inv0);
        float2 o1 = make_float2(oa[nt][2] * inv1, oa[nt][3] * inv1);
        *(float2*)(out + orow0 + d) = o0;
        *(float2*)(out + orow1 + d) = o1;
        lmax = fmaxf(lmax, fmaxf(fmaxf(fabsf(o0.x), fabsf(o0.y)),
                                 fmaxf(fabsf(o1.x), fabsf(o1.y))));
    }
#pragma unroll
    for (int off = 16; off >= 1; off >>= 1)
        lmax = fmaxf(lmax, __shfl_xor_sync(0xffffffffu, lmax, off));
    __syncthreads();                       // Q smem no longer needed
    float* red = (float*)sm;
    if (lane == 0) red[wid] = lmax;
    __syncthreads();
    if (tid == 0) {
        float bm = red[0];
#pragma unroll
        for (int w = 1; w < 8; w++) bm = fmaxf(bm, red[w]);
        atomicMax(&g_maxA, __float_as_uint(bm));
    }
}

// ---------------------------------------------------------------------------
// int8 2-digit GEMM + bias (R7 kernel, verbatim)
// ---------------------------------------------------------------------------
#define IA_PL 6144
#define IB_PL 3072
#define ISTG (2 * IA_PL + 2 * IB_PL)
#define INST 4
#define INT8_SMEM (INST * ISTG)      // 73728

__global__ __launch_bounds__(256, 2)
void gemm_int8(const int8_t* __restrict__ A1, const int8_t* __restrict__ A2,
               const int8_t* __restrict__ W1, const int8_t* __restrict__ W2,
               const float* __restrict__ bias, float* __restrict__ C,
               int M, int N, int K)
{
    extern __shared__ uint32_t smem[];
    const uint32_t sb = (uint32_t)__cvta_generic_to_shared(smem);

    const int tid  = threadIdx.x;
    const int warp = tid >> 5;
    const int lane = tid & 31;
    const int g = lane >> 2;
    const int t = lane & 3;
    const int wm = (warp >> 1) * 32;
    const int wn = (warp & 1) * 32;
    const int brow = blockIdx.y * 128;
    const int bcol = blockIdx.x * 64;

    const int arow = tid >> 1, ahalf = tid & 1;
    const int wrow = tid >> 2, whalf = (tid >> 1) & 1, wpl = tid & 1;
    const int8_t* gA[2] = { A1 + (size_t)(brow + arow) * K + ahalf * 16,
                            A2 + (size_t)(brow + arow) * K + ahalf * 16 };
    const int8_t* gW   = (wpl ? W2 : W1) + (size_t)(bcol + wrow) * K + whalf * 16;

    auto issue_chunk = [&](int c) {
        const uint32_t base = sb + (uint32_t)((c & (INST - 1)) * ISTG);
        const int k0 = c * 32;
        cp16(base + 0 * IA_PL + arow * 48 + ahalf * 16, gA[0] + k0);
        cp16(base + 1 * IA_PL + arow * 48 + ahalf * 16, gA[1] + k0);
        cp16(base + 2 * IA_PL + wpl * IB_PL + wrow * 48 + whalf * 16, gW + k0);
        CP_COMMIT();
    };

    const int laA = (lane & 7) + ((lane >> 3) & 1) * 8;
    const uint32_t kaA = (uint32_t)(((lane >> 4) & 1) * 16);
    const int laB = (lane & 7) + ((lane >> 4) & 1) * 8;
    const uint32_t kaB = (uint32_t)(((lane >> 3) & 1) * 16);

    int acc1[2][4][4], acc2[2][4][4];
#pragma unroll
    for (int mt = 0; mt < 2; mt++)
#pragma unroll
        for (int nt = 0; nt < 4; nt++)
#pragma unroll
            for (int r = 0; r < 4; r++) { acc1[mt][nt][r] = 0; acc2[mt][nt][r] = 0; }

    const int NC = K / 32;
#pragma unroll
    for (int s = 0; s < INST - 1; s++) issue_chunk(s);

    for (int c = 0; c < NC; c++) {
        CP_WAIT(INST - 2);
        __syncthreads();
        if (c + INST - 1 < NC) issue_chunk(c + INST - 1);

        const uint32_t base = sb + (uint32_t)((c & (INST - 1)) * ISTG);
        uint32_t b1[4][2], b2[4][2];
#pragma unroll
        for (int np = 0; np < 2; np++) {
            const uint32_t ro = (uint32_t)((wn + np * 16 + laB) * 48) + kaB;
            ldsm4(b1[2 * np][0], b1[2 * np][1], b1[2 * np + 1][0], b1[2 * np + 1][1],
                  base + 2 * IA_PL + ro);
            ldsm4(b2[2 * np][0], b2[2 * np][1], b2[2 * np + 1][0], b2[2 * np + 1][1],
                  base + 2 * IA_PL + IB_PL + ro);
        }
#pragma unroll
        for (int mt = 0; mt < 2; mt++) {
            const uint32_t ro = (uint32_t)((wm + mt * 16 + laA) * 48) + kaA;
            uint32_t a1f[4], a2f[4];
            ldsm4(a1f[0], a1f[1], a1f[2], a1f[3], base + ro);
            ldsm4(a2f[0], a2f[1], a2f[2], a2f[3], base + IA_PL + ro);
#pragma unroll
            for (int nt = 0; nt < 4; nt++) {
                mma_s8(acc1[mt][nt], a1f[0], a1f[1], a1f[2], a1f[3],
                       b1[nt][0], b1[nt][1]);
                mma_s8(acc2[mt][nt], a1f[0], a1f[1], a1f[2], a1f[3],
                       b2[nt][0], b2[nt][1]);
                mma_s8(acc2[mt][nt], a2f[0], a2f[1], a2f[2], a2f[3],
                       b1[nt][0], b1[nt][1]);
            }
        }
    }

    const float maxA = fmaxf(__uint_as_float(g_maxA), 1e-30f);
    const float maxW = fmaxf(__uint_as_float(g_maxW), 1e-30f);
    const float inv = (maxA * maxW) / (32512.0f * 32512.0f);

#pragma unroll
    for (int nt = 0; nt < 4; nt++) {
        const int col = bcol + wn + nt * 8 + 2 * t;
        const float2 bv = *(const float2*)(bias + col);
#pragma unroll
        for (int mt = 0; mt < 2; mt++) {
            const int row0 = brow + wm + mt * 16 + g;
            float2 o0, o1;
            o0.x = (65536.0f * (float)acc1[mt][nt][0] + 256.0f * (float)acc2[mt][nt][0]) * inv + bv.x;
            o0.y = (65536.0f * (float)acc1[mt][nt][1] + 256.0f * (float)acc2[mt][nt][1]) * inv + bv.y;
            o1.x = (65536.0f * (float)acc1[mt][nt][2] + 256.0f * (float)acc2[mt][nt][2]) * inv + bv.x;
            o1.y = (65536.0f * (float)acc1[mt][nt][3] + 256.0f * (float)acc2[mt][nt][3]) * inv + bv.y;
            *(float2*)(C + (size_t)row0 * N + col)       = o0;
            *(float2*)(C + (size_t)(row0 + 8) * N + col) = o1;
        }
    }
}

// ---------------------------------------------------------------------------
// Launch
// ---------------------------------------------------------------------------
extern "C" void kernel_launch(void* const* d_in, const int* in_sizes, int n_in,
                              void* d_out, int out_size)
{
    const float* hidden = (const float*)d_in[0];
    const float* w_attn = (const float*)d_in[1];
    const float* b_attn = (const float*)d_in[2];
    const float* w_proj = (const float*)d_in[3];
    const float* b_proj = (const float*)d_in[4];
    float* out = (float*)d_out;

    uint32_t *qh, *ql;
    float* attn;
    int8_t *a1, *a2, *w1, *w2;
    unsigned* mW;
    cudaGetSymbolAddress((void**)&qh, g_qh);
    cudaGetSymbolAddress((void**)&ql, g_ql);
    cudaGetSymbolAddress((void**)&attn, g_attn);
    cudaGetSymbolAddress((void**)&a1, g_a1);
    cudaGetSymbolAddress((void**)&a2, g_a2);
    cudaGetSymbolAddress((void**)&w1, g_w1);
    cudaGetSymbolAddress((void**)&w2, g_w2);
    cudaGetSymbolAddress((void**)&mW, g_maxW);

    static bool attr_set = false;
    if (!attr_set) {
        cudaFuncSetAttribute(flash_bf16x3,
                             cudaFuncAttributeMaxDynamicSharedMemorySize, FL_SMEM);
        cudaFuncSetAttribute(gemm_int8,
                             cudaFuncAttributeMaxDynamicSharedMemorySize, INT8_SMEM);
        attr_set = true;
    }

    // 0) w_proj max + transpose/quantize
    maxabs_kernel<<<256, 256>>>(w_proj, HIDDEN * HIDDEN, mW);
    {
        dim3 gp(HIDDEN / 32, HIDDEN / 64);
        transpose_quant_kernel<<<gp, 256>>>(w_proj, w1, w2, HIDDEN, HIDDEN);
    }
    // 1) QKV projection -> split planes (bf16 Q,K; fp16 V)
    {
        dim3 grid(QKV_N / 128, M_TOK / 128);
        gemm_bf16x3<<<grid, 256>>>(hidden, w_attn, b_attn,
                                   nullptr, qh, ql,
                                   M_TOK, QKV_N, HIDDEN, 1);
    }
    // 2) flash attention v4 -> fp32 attn + g_maxA
    {
        dim3 grid(SEQ / 128, NHEAD, BATCH);
        flash_bf16x3<<<grid, 256, FL_SMEM>>>(qh, ql, attn);
    }
    // 3) quantize attn to int8 digits
    {
        const int n = M_TOK * HIDDEN;
        quant_attn_kernel<<<(n + 255) / 256, 256>>>(attn, a1, a2, n);
    }
    // 4) output projection via int8 IMMA
    {
        dim3 grid(HIDDEN / 64, M_TOK / 128);
        gemm_int8<<<grid, 256, INT8_SMEM>>>(a1, a2, w1, w2, b_proj, out,
                                            M_TOK, HIDDEN, HIDDEN);
    }
}